// round 7
// baseline (speedup 1.0000x reference)
#include <cuda_runtime.h>
#include <cstdint>

#define B_ 4
#define S_ 2048
#define D_ 1024
#define H_ 16
#define DK_ 64
#define M_ (B_ * S_)   // 8192

// Scratch (device globals — no allocation allowed)
__device__ float g_q[M_ * D_];     // [B,H,S,DK] tf32, q pre-scaled by 0.125*log2e
__device__ float g_k[M_ * D_];     // [B,H,S,DK] tf32
__device__ float g_v[M_ * D_];     // [B,H,S,DK] tf32
__device__ float g_vT[M_ * D_];    // [B,H,DK,S] tf32 (V transposed per head)
__device__ float g_x[M_ * D_];     // [B,S,D] attention out, tf32-rounded
__device__ float g_rq[M_ * D_];    // tf32-rounded copies of raw inputs
__device__ float g_rk[M_ * D_];
__device__ float g_rv[M_ * D_];
__device__ float g_rwq[D_ * D_];
__device__ float g_rwk[D_ * D_];
__device__ float g_rwv[D_ * D_];
__device__ float g_rwo[D_ * D_];
__device__ int   g_mflag[16 * 32];

__device__ __forceinline__ float to_tf32(float x) {
    float r;
    asm("cvt.rna.tf32.f32 %0, %1;" : "=f"(r) : "f"(x));
    return r;
}

__device__ __forceinline__ void mma8(float c[4], float a0, float a1, float a2, float a3,
                                     float b0, float b1) {
    asm volatile(
        "mma.sync.aligned.m16n8k8.row.col.f32.tf32.tf32.f32 "
        "{%0,%1,%2,%3}, {%4,%5,%6,%7}, {%8,%9}, {%0,%1,%2,%3};"
        : "+f"(c[0]), "+f"(c[1]), "+f"(c[2]), "+f"(c[3])
        : "r"(__float_as_uint(a0)), "r"(__float_as_uint(a1)),
          "r"(__float_as_uint(a2)), "r"(__float_as_uint(a3)),
          "r"(__float_as_uint(b0)), "r"(__float_as_uint(b1)));
}

__device__ __forceinline__ uint32_t smem_u32(const void* p) {
    return (uint32_t)__cvta_generic_to_shared(p);
}
__device__ __forceinline__ void cp_async16(uint32_t dst, const float* src) {
    asm volatile("cp.async.ca.shared.global [%0], [%1], 16;" :: "r"(dst), "l"(src));
}
#define CP_COMMIT() asm volatile("cp.async.commit_group;")
#define CP_WAIT1()  asm volatile("cp.async.wait_group 1;")
#define CP_WAIT0()  asm volatile("cp.async.wait_group 0;")

// ---------------------------------------------------------------------------
// Fused prepass: tf32 rounding (y<7) + mask tile prescan (y==7).
// ---------------------------------------------------------------------------
__global__ __launch_bounds__(256) void pre_kernel(
    const float* __restrict__ q, const float* __restrict__ k, const float* __restrict__ v,
    const float* __restrict__ wq, const float* __restrict__ wk,
    const float* __restrict__ wv, const float* __restrict__ wo,
    const int* __restrict__ mask)
{
    const int which = blockIdx.y;
    if (which == 7) {
        // mask prescan: 512 tiles of 128x64
        if (blockIdx.x >= 512) return;
        const int qt = blockIdx.x >> 5, kt = blockIdx.x & 31;
        const int tid = threadIdx.x;
        const int r = tid >> 1, h = tid & 1;
        const int* p = mask + (qt * 128 + r) * S_ + kt * 64 + h * 32;
        bool ok = true;
#pragma unroll
        for (int j = 0; j < 8; j++) {
            int4 mv = *(const int4*)(p + j * 4);
            ok &= (mv.x != 0) & (mv.y != 0) & (mv.z != 0) & (mv.w != 0);
        }
        const int all = __syncthreads_and((int)ok);
        if (tid == 0) g_mflag[qt * 32 + kt] = all;
        return;
    }
    const float* src;
    float* dst;
    int n4;
    if (which < 3) {
        n4 = M_ * D_ / 4;
        src = (which == 0) ? q : (which == 1) ? k : v;
        dst = (which == 0) ? g_rq : (which == 1) ? g_rk : g_rv;
    } else {
        n4 = D_ * D_ / 4;
        src = (which == 3) ? wq : (which == 4) ? wk : (which == 5) ? wv : wo;
        dst = (which == 3) ? g_rwq : (which == 4) ? g_rwk : (which == 5) ? g_rwv : g_rwo;
    }
    const int stride = gridDim.x * blockDim.x;
    for (int i = blockIdx.x * blockDim.x + threadIdx.x; i < n4; i += stride) {
        float4 t = ((const float4*)src)[i];
        ((float4*)dst)[i] =
            make_float4(to_tf32(t.x), to_tf32(t.y), to_tf32(t.z), to_tf32(t.w));
    }
}

// ---------------------------------------------------------------------------
// V transpose: g_v [bh][s][dk] -> g_vT [bh][dk][s]
// ---------------------------------------------------------------------------
__global__ __launch_bounds__(256) void vtrans_kernel()
{
    __shared__ float t[32][33];
    const int s0 = blockIdx.x * 32, d0 = blockIdx.y * 32, bh = blockIdx.z;
    const float* src = g_v + bh * S_ * DK_;
    float* dst = g_vT + bh * DK_ * S_;
    const int tx = threadIdx.x & 31, ty = threadIdx.x >> 5;
#pragma unroll
    for (int i = 0; i < 4; i++)
        t[ty + i * 8][tx] = src[(s0 + ty + i * 8) * DK_ + d0 + tx];
    __syncthreads();
#pragma unroll
    for (int i = 0; i < 4; i++)
        dst[(d0 + ty + i * 8) * S_ + s0 + tx] = t[tx][ty + i * 8];
}

// ---------------------------------------------------------------------------
// tf32 tensor-core GEMM, 3-stage cp.async pipeline, perm-float2 frag loads.
// out[m,n] = sum_k X[m,k]*W[n,k] + bias[n].  BM=BN=128, BK=16, 256 thr.
// k-slot permutation: slot tg <- logical col 2tg, slot tg+4 <- col 2tg+1,
// applied identically to A and B => dot product unchanged.
// ---------------------------------------------------------------------------
#define GSTG 2560              // 128*20 floats per stage per tensor
#define GEMM_SMEM_BYTES (2 * 3 * GSTG * 4)

template <bool SPLIT>
__device__ __forceinline__ void gemm_tc(
    float* As, float* Bs,
    const float* __restrict__ X, const float* __restrict__ W,
    const float* __restrict__ bias, float* __restrict__ out, float scale)
{
    const int tid = threadIdx.x;
    const int lane = tid & 31, wid = tid >> 5;
    const int g = lane >> 2, tg = lane & 3;
    const int wm = wid >> 1, wn = wid & 1;
    const int m0 = blockIdx.y * 128, n0 = blockIdx.x * 128;

    const uint32_t AsU = smem_u32(As), BsU = smem_u32(Bs);
    const int lr = tid >> 1;
    const int lsg = (tid & 1) * 8;

    const float* xrow = X + (long long)(m0 + lr) * D_ + lsg;
    const float* wrow = W + (long long)(n0 + lr) * D_ + lsg;
    const uint32_t adst = AsU + (uint32_t)(lr * 20 + lsg) * 4;
    const uint32_t bdst = BsU + (uint32_t)(lr * 20 + lsg) * 4;

#define G_ISSUE(s, kb)                                        \
    do {                                                      \
        const float* xs = xrow + (kb) * 16;                   \
        const float* ws = wrow + (kb) * 16;                   \
        const uint32_t so = (uint32_t)((s) * GSTG) * 4;       \
        cp_async16(adst + so, xs);                            \
        cp_async16(adst + so + 16, xs + 4);                   \
        cp_async16(bdst + so, ws);                            \
        cp_async16(bdst + so + 16, ws + 4);                   \
    } while (0)

    float acc[2][8][4];
#pragma unroll
    for (int mt = 0; mt < 2; mt++)
#pragma unroll
        for (int nt = 0; nt < 8; nt++)
#pragma unroll
            for (int i = 0; i < 4; i++) acc[mt][nt][i] = 0.0f;

    G_ISSUE(0, 0);
    CP_COMMIT();
    G_ISSUE(1, 1);
    CP_COMMIT();

    for (int it = 0; it < 64; it++) {
        CP_WAIT1();
        __syncthreads();
        int nx = it + 2;
        if (nx >= 64) nx -= 64;
        G_ISSUE((it + 2) % 3, nx);
        CP_COMMIT();

        const float* Ab = As + (it % 3) * GSTG;
        const float* Bb = Bs + (it % 3) * GSTG;
#pragma unroll
        for (int kk = 0; kk < 2; kk++) {
            const int kc = kk * 8 + tg * 2;   // logical cols 2tg,2tg+1 of k-block
            float2 a0[2], a1[2];
#pragma unroll
            for (int mt = 0; mt < 2; mt++) {
                const int rb = wm * 32 + mt * 16 + g;
                a0[mt] = *(const float2*)&Ab[rb * 20 + kc];
                a1[mt] = *(const float2*)&Ab[(rb + 8) * 20 + kc];
            }
#pragma unroll
            for (int nt = 0; nt < 8; nt++) {
                const float2 b = *(const float2*)&Bb[(wn * 64 + nt * 8 + g) * 20 + kc];
                mma8(acc[0][nt], a0[0].x, a1[0].x, a0[0].y, a1[0].y, b.x, b.y);
                mma8(acc[1][nt], a0[1].x, a1[1].x, a0[1].y, a1[1].y, b.x, b.y);
            }
        }
    }
#undef G_ISSUE

#pragma unroll
    for (int mt = 0; mt < 2; mt++) {
        const int r0 = m0 + wm * 32 + mt * 16 + g;
#pragma unroll
        for (int nt = 0; nt < 8; nt++) {
            const int c = n0 + wn * 64 + nt * 8 + tg * 2;
            const float bv0 = bias[c], bv1 = bias[c + 1];
            float v00 = acc[mt][nt][0] + bv0, v01 = acc[mt][nt][1] + bv1;
            float v10 = acc[mt][nt][2] + bv0, v11 = acc[mt][nt][3] + bv1;
            if (SPLIT) {
                v00 = to_tf32(v00 * scale); v01 = to_tf32(v01 * scale);
                v10 = to_tf32(v10 * scale); v11 = to_tf32(v11 * scale);
                const int h = c >> 6, dk = c & 63;
                const int bb = r0 >> 11, ss = r0 & 2047;
                float* o0 = &out[(((bb * H_ + h) * S_) + ss) * DK_ + dk];
                *(float2*)o0 = make_float2(v00, v01);
                *(float2*)(o0 + 8 * DK_) = make_float2(v10, v11);
            } else {
                *(float2*)&out[r0 * D_ + c] = make_float2(v00, v01);
                *(float2*)&out[(r0 + 8) * D_ + c] = make_float2(v10, v11);
            }
        }
    }
}

// 0.125 * log2(e)
#define QSCALE 0.1803368801111204f

__global__ __launch_bounds__(256, 2) void qkv_kernel(
    const float* __restrict__ bq, const float* __restrict__ bk,
    const float* __restrict__ bv)
{
    extern __shared__ __align__(16) float sm[];
    float* As = sm;
    float* Bs = sm + 3 * GSTG;
    if (blockIdx.z == 0)      gemm_tc<true>(As, Bs, g_rq, g_rwq, bq, g_q, QSCALE);
    else if (blockIdx.z == 1) gemm_tc<true>(As, Bs, g_rk, g_rwk, bk, g_k, 1.0f);
    else                      gemm_tc<true>(As, Bs, g_rv, g_rwv, bv, g_v, 1.0f);
}

__global__ __launch_bounds__(256, 2) void oproj_kernel(
    const float* __restrict__ bo, float* __restrict__ out)
{
    extern __shared__ __align__(16) float sm[];
    float* As = sm;
    float* Bs = sm + 3 * GSTG;
    gemm_tc<false>(As, Bs, g_x, g_rwo, bo, out, 1.0f);
}

// ---------------------------------------------------------------------------
// Flash attention, tf32 mma, XOR-swizzled stride-64 smem (96KB, 2 CTA/SM),
// P in registers, double-buffered 16B cp.async K/V, base-2 softmax.
// ---------------------------------------------------------------------------
#define ATQ (128 * 64)
#define ATKV (64 * 64)
#define ATTN_SMEM_BYTES ((ATQ + 4 * ATKV) * 4)   // 98304 B = 96KB

__global__ __launch_bounds__(256, 2) void attn_kernel(const int* __restrict__ mask)
{
    extern __shared__ __align__(16) float sm[];
    float* Qs = sm;
    float* Ks = sm + ATQ;            // 2 stages
    float* Vt = sm + ATQ + 2 * ATKV; // 2 stages (dk rows x kv cols)

    const int tid = threadIdx.x;
    const int lane = tid & 31, wid = tid >> 5;
    const int g = lane >> 2, tg = lane & 3;
    const int w16 = wid * 16;
    const int q0 = blockIdx.x * 128;
    const int bh = blockIdx.y;

    const float* Qg = g_q + bh * S_ * DK_;
    const float* Kg = g_k + bh * S_ * DK_;
    const float* Vg = g_vT + bh * DK_ * S_;

    const uint32_t QsU = smem_u32(Qs), KsU = smem_u32(Ks), VtU = smem_u32(Vt);
    const int r = tid >> 2, qd = tid & 3;
    const int rsw = (r & 7) * 8;     // swizzle term for loader row r

    // Q tile (128x64) via cp.async, swizzled layout
    {
        const int qr = tid >> 1, hf = tid & 1;
        const int qsw = (qr & 7) * 8;
        const float* src = Qg + (q0 + qr) * DK_ + hf * 32;
        const uint32_t dstb = QsU + (uint32_t)(qr * 64) * 4;
#pragma unroll
        for (int j = 0; j < 8; j++)
            cp_async16(dstb + (uint32_t)((hf * 32 + j * 4) ^ qsw) * 4, src + j * 4);
    }

#define KV_ISSUE(s, t)                                                          \
    do {                                                                        \
        const float* ksrc = Kg + ((t) * 64 + r) * DK_ + qd * 16;                \
        const float* vsrc = Vg + r * S_ + (t) * 64 + qd * 16;                   \
        const uint32_t kdb = KsU + (uint32_t)((s) * ATKV + r * 64) * 4;         \
        const uint32_t vdb = VtU + (uint32_t)((s) * ATKV + r * 64) * 4;         \
        _Pragma("unroll")                                                       \
        for (int j = 0; j < 4; j++) {                                           \
            const uint32_t co = (uint32_t)((qd * 16 + j * 4) ^ rsw) * 4;        \
            cp_async16(kdb + co, ksrc + j * 4);                                 \
            cp_async16(vdb + co, vsrc + j * 4);                                 \
        }                                                                       \
    } while (0)

    KV_ISSUE(0, 0);
    CP_COMMIT();
    KV_ISSUE(1, 1);
    CP_COMMIT();

    float mrow0 = -1e30f, mrow1 = -1e30f;
    float lrow0 = 0.0f, lrow1 = 0.0f;
    float o[8][4];
#pragma unroll
    for (int nt = 0; nt < 8; nt++)
#pragma unroll
        for (int i = 0; i < 4; i++) o[nt][i] = 0.0f;

    for (int kt = 0; kt < 32; kt++) {
        CP_WAIT1();
        __syncthreads();
        const float* Ksb = Ks + (kt & 1) * ATKV;
        const float* Vtb = Vt + (kt & 1) * ATKV;

        // S = Q @ K^T (warp: 16x64)
        float s[8][4];
#pragma unroll
        for (int nt = 0; nt < 8; nt++)
#pragma unroll
            for (int i = 0; i < 4; i++) s[nt][i] = 0.0f;

#pragma unroll
        for (int kk = 0; kk < 8; kk++) {
            const int fo = 8 * (kk ^ g) + tg * 2;    // swizzled frag col offset
            const float2 aA = *(const float2*)&Qs[(w16 + g) * 64 + fo];
            const float2 aB = *(const float2*)&Qs[(w16 + 8 + g) * 64 + fo];
#pragma unroll
            for (int nt = 0; nt < 8; nt++) {
                const float2 bv = *(const float2*)&Ksb[(nt * 8 + g) * 64 + fo];
                mma8(s[nt], aA.x, aB.x, aA.y, aB.y, bv.x, bv.y);
            }
        }

        // Mask (rare path)
        if (!g_mflag[blockIdx.x * 32 + kt]) {
            const int k0 = kt * 64;
            const int* mp0 = mask + (q0 + w16 + g) * S_ + k0 + tg * 2;
            const int* mp1 = mp0 + 8 * S_;
#pragma unroll
            for (int nt = 0; nt < 8; nt++) {
                const int2 m0v = *(const int2*)(mp0 + nt * 8);
                const int2 m1v = *(const int2*)(mp1 + nt * 8);
                if (m0v.x == 0) s[nt][0] = -1e9f;
                if (m0v.y == 0) s[nt][1] = -1e9f;
                if (m1v.x == 0) s[nt][2] = -1e9f;
                if (m1v.y == 0) s[nt][3] = -1e9f;
            }
        }

        // Online softmax (base 2); P stays in registers (s[])
        float mx0 = -1e30f, mx1 = -1e30f;
#pragma unroll
        for (int nt = 0; nt < 8; nt++) {
            mx0 = fmaxf(mx0, fmaxf(s[nt][0], s[nt][1]));
            mx1 = fmaxf(mx1, fmaxf(s[nt][2], s[nt][3]));
        }
        mx0 = fmaxf(mx0, __shfl_xor_sync(0xffffffffu, mx0, 1));
        mx0 = fmaxf(mx0, __shfl_xor_sync(0xffffffffu, mx0, 2));
        mx1 = fmaxf(mx1, __shfl_xor_sync(0xffffffffu, mx1, 1));
        mx1 = fmaxf(mx1, __shfl_xor_sync(0xffffffffu, mx1, 2));
        const float mn0 = fmaxf(mrow0, mx0);
        const float mn1 = fmaxf(mrow1, mx1);
        const float al0 = exp2f(mrow0 - mn0);
        const float al1 = exp2f(mrow1 - mn1);
        mrow0 = mn0; mrow1 = mn1;

        float sum0 = 0.0f, sum1 = 0.0f;
#pragma unroll
        for (int nt = 0; nt < 8; nt++) {
            const float p0 = exp2f(s[nt][0] - mn0);
            const float p1 = exp2f(s[nt][1] - mn0);
            const float p2 = exp2f(s[nt][2] - mn1);
            const float p3 = exp2f(s[nt][3] - mn1);
            sum0 += p0 + p1;
            sum1 += p2 + p3;
            s[nt][0] = to_tf32(p0);
            s[nt][1] = to_tf32(p1);
            s[nt][2] = to_tf32(p2);
            s[nt][3] = to_tf32(p3);
            o[nt][0] *= al0; o[nt][1] *= al0;
            o[nt][2] *= al1; o[nt][3] *= al1;
        }
        sum0 += __shfl_xor_sync(0xffffffffu, sum0, 1);
        sum0 += __shfl_xor_sync(0xffffffffu, sum0, 2);
        sum1 += __shfl_xor_sync(0xffffffffu, sum1, 1);
        sum1 += __shfl_xor_sync(0xffffffffu, sum1, 2);
        lrow0 = lrow0 * al0 + sum0;
        lrow1 = lrow1 * al1 + sum1;

        // O += P @ V (C-fragment reused as A-fragment; same k-permutation)
#pragma unroll
        for (int kk = 0; kk < 8; kk++) {
#pragma unroll
            for (int nt = 0; nt < 8; nt++) {
                const float2 bv =
                    *(const float2*)&Vtb[(nt * 8 + g) * 64 + 8 * (kk ^ g) + tg * 2];
                mma8(o[nt], s[kk][0], s[kk][2], s[kk][1], s[kk][3], bv.x, bv.y);
            }
        }

        __syncthreads();   // all warps done with stage (kt&1)
        KV_ISSUE(kt & 1, (kt + 2) & 31);   // wrap: last 2 iters load dead data
        CP_COMMIT();
    }
#undef KV_ISSUE

    CP_WAIT0();  // drain async copies before CTA exit

    // Normalize, round to tf32 (consumed via cp.async by oproj), store [B,S,D]
    const float inv0 = 1.0f / lrow0;
    const float inv1 = 1.0f / lrow1;
    const int bb = bh >> 4, h = bh & 15;
    const int r0 = q0 + w16 + g;
    float* O0 = &g_x[(bb * S_ + r0) * D_ + h * DK_ + tg * 2];
    float* O1 = O0 + 8 * D_;
#pragma unroll
    for (int nt = 0; nt < 8; nt++) {
        *(float2*)(O0 + nt * 8) =
            make_float2(to_tf32(o[nt][0] * inv0), to_tf32(o[nt][1] * inv0));
        *(float2*)(O1 + nt * 8) =
            make_float2(to_tf32(o[nt][2] * inv1), to_tf32(o[nt][3] * inv1));
    }
}

// ---------------------------------------------------------------------------
extern "C" void kernel_launch(void* const* d_in, const int* in_sizes, int n_in,
                              void* d_out, int out_size)
{
    (void)in_sizes; (void)n_in; (void)out_size;
    const float* q    = (const float*)d_in[0];
    const float* k    = (const float*)d_in[1];
    const float* v    = (const float*)d_in[2];
    const int*   mask = (const int*)d_in[3];
    const float* wq   = (const float*)d_in[4];
    const float* bq   = (const float*)d_in[5];
    const float* wk   = (const float*)d_in[6];
    const float* bk   = (const float*)d_in[7];
    const float* wv   = (const float*)d_in[8];
    const float* bv   = (const float*)d_in[9];
    const float* wo   = (const float*)d_in[10];
    const float* bo   = (const float*)d_in[11];
    float* out = (float*)d_out;

    static bool attrs_set = false;
    if (!attrs_set) {
        cudaFuncSetAttribute(qkv_kernel, cudaFuncAttributeMaxDynamicSharedMemorySize,
                             GEMM_SMEM_BYTES);
        cudaFuncSetAttribute(oproj_kernel, cudaFuncAttributeMaxDynamicSharedMemorySize,
                             GEMM_SMEM_BYTES);
        cudaFuncSetAttribute(attn_kernel, cudaFuncAttributeMaxDynamicSharedMemorySize,
                             ATTN_SMEM_BYTES);
        attrs_set = true;
    }

    // Fused prepass: tf32 rounding + mask prescan
    dim3 gpre(1024, 8);
    pre_kernel<<<gpre, 256>>>(q, k, v, wq, wk, wv, wo, mask);

    // QKV projections
    dim3 gqkv(D_ / 128, M_ / 128, 3);
    qkv_kernel<<<gqkv, 256, GEMM_SMEM_BYTES>>>(bq, bk, bv);

    // V transpose
    dim3 gvt(S_ / 32, DK_ / 32, B_ * H_);
    vtrans_kernel<<<gvt, 256>>>();

    // Attention (4th launch — target for the ncu capture slot)
    dim3 gattn(S_ / 128, B_ * H_);
    attn_kernel<<<gattn, 256, ATTN_SMEM_BYTES>>>(mask);

    // Output projection
    dim3 gop(D_ / 128, M_ / 128);
    oproj_kernel<<<gop, 256, GEMM_SMEM_BYTES>>>(bo, out);
}

// round 8
// speedup vs baseline: 1.1438x; 1.1438x over previous
#include <cuda_runtime.h>
#include <cstdint>

#define B_ 4
#define S_ 2048
#define D_ 1024
#define H_ 16
#define DK_ 64
#define M_ (B_ * S_)   // 8192

// Scratch (device globals — no allocation allowed)
__device__ float g_q[M_ * D_];     // [B,H,S,DK] tf32, q pre-scaled by 0.125*log2e
__device__ float g_k[M_ * D_];     // [B,H,S,DK] tf32
__device__ float g_v[M_ * D_];     // [B,H,S,DK] tf32
__device__ float g_vT[M_ * D_];    // [B,H,DK,S] tf32 (V transposed per head)
__device__ float g_x[M_ * D_];     // [B,S,D] attention out, tf32-rounded
__device__ float g_rq[M_ * D_];    // tf32-rounded copies of raw inputs
__device__ float g_rk[M_ * D_];
__device__ float g_rv[M_ * D_];
__device__ float g_rwq[D_ * D_];
__device__ float g_rwk[D_ * D_];
__device__ float g_rwv[D_ * D_];
__device__ float g_rwo[D_ * D_];
__device__ int   g_mflag[16 * 32];

__device__ __forceinline__ float to_tf32(float x) {
    float r;
    asm("cvt.rna.tf32.f32 %0, %1;" : "=f"(r) : "f"(x));
    return r;
}

__device__ __forceinline__ void mma8(float c[4], float a0, float a1, float a2, float a3,
                                     float b0, float b1) {
    asm volatile(
        "mma.sync.aligned.m16n8k8.row.col.f32.tf32.tf32.f32 "
        "{%0,%1,%2,%3}, {%4,%5,%6,%7}, {%8,%9}, {%0,%1,%2,%3};"
        : "+f"(c[0]), "+f"(c[1]), "+f"(c[2]), "+f"(c[3])
        : "r"(__float_as_uint(a0)), "r"(__float_as_uint(a1)),
          "r"(__float_as_uint(a2)), "r"(__float_as_uint(a3)),
          "r"(__float_as_uint(b0)), "r"(__float_as_uint(b1)));
}

__device__ __forceinline__ uint32_t smem_u32(const void* p) {
    return (uint32_t)__cvta_generic_to_shared(p);
}
__device__ __forceinline__ void cp_async16(uint32_t dst, const float* src) {
    asm volatile("cp.async.ca.shared.global [%0], [%1], 16;" :: "r"(dst), "l"(src));
}
#define CP_COMMIT() asm volatile("cp.async.commit_group;")
#define CP_WAIT1()  asm volatile("cp.async.wait_group 1;")
#define CP_WAIT0()  asm volatile("cp.async.wait_group 0;")

// ---------------------------------------------------------------------------
// Fused prepass: tf32 rounding (y<7) + mask tile prescan (y==7).
// ---------------------------------------------------------------------------
__global__ __launch_bounds__(256) void pre_kernel(
    const float* __restrict__ q, const float* __restrict__ k, const float* __restrict__ v,
    const float* __restrict__ wq, const float* __restrict__ wk,
    const float* __restrict__ wv, const float* __restrict__ wo,
    const int* __restrict__ mask)
{
    const int which = blockIdx.y;
    if (which == 7) {
        if (blockIdx.x >= 512) return;
        const int qt = blockIdx.x >> 5, kt = blockIdx.x & 31;
        const int tid = threadIdx.x;
        const int r = tid >> 1, h = tid & 1;
        const int* p = mask + (qt * 128 + r) * S_ + kt * 64 + h * 32;
        bool ok = true;
#pragma unroll
        for (int j = 0; j < 8; j++) {
            int4 mv = *(const int4*)(p + j * 4);
            ok &= (mv.x != 0) & (mv.y != 0) & (mv.z != 0) & (mv.w != 0);
        }
        const int all = __syncthreads_and((int)ok);
        if (tid == 0) g_mflag[qt * 32 + kt] = all;
        return;
    }
    const float* src;
    float* dst;
    int n4;
    if (which < 3) {
        n4 = M_ * D_ / 4;
        src = (which == 0) ? q : (which == 1) ? k : v;
        dst = (which == 0) ? g_rq : (which == 1) ? g_rk : g_rv;
    } else {
        n4 = D_ * D_ / 4;
        src = (which == 3) ? wq : (which == 4) ? wk : (which == 5) ? wv : wo;
        dst = (which == 3) ? g_rwq : (which == 4) ? g_rwk : (which == 5) ? g_rwv : g_rwo;
    }
    const int stride = gridDim.x * blockDim.x;
    for (int i = blockIdx.x * blockDim.x + threadIdx.x; i < n4; i += stride) {
        float4 t = ((const float4*)src)[i];
        ((float4*)dst)[i] =
            make_float4(to_tf32(t.x), to_tf32(t.y), to_tf32(t.z), to_tf32(t.w));
    }
}

// ---------------------------------------------------------------------------
// V transpose: g_v [bh][s][dk] -> g_vT [bh][dk][s]
// ---------------------------------------------------------------------------
__global__ __launch_bounds__(256) void vtrans_kernel()
{
    __shared__ float t[32][33];
    const int s0 = blockIdx.x * 32, d0 = blockIdx.y * 32, bh = blockIdx.z;
    const float* src = g_v + bh * S_ * DK_;
    float* dst = g_vT + bh * DK_ * S_;
    const int tx = threadIdx.x & 31, ty = threadIdx.x >> 5;
#pragma unroll
    for (int i = 0; i < 4; i++)
        t[ty + i * 8][tx] = src[(s0 + ty + i * 8) * DK_ + d0 + tx];
    __syncthreads();
#pragma unroll
    for (int i = 0; i < 4; i++)
        dst[(d0 + ty + i * 8) * S_ + s0 + tx] = t[tx][ty + i * 8];
}

// ---------------------------------------------------------------------------
// tf32 tensor-core GEMM, 3-stage cp.async pipeline (reverted to R6 inner loop).
// ---------------------------------------------------------------------------
#define GSTG 2560              // 128*20 floats per stage per tensor
#define GEMM_SMEM_BYTES (2 * 3 * GSTG * 4)

template <bool SPLIT>
__device__ __forceinline__ void gemm_tc(
    float* As, float* Bs,
    const float* __restrict__ X, const float* __restrict__ W,
    const float* __restrict__ bias, float* __restrict__ out, float scale)
{
    const int tid = threadIdx.x;
    const int lane = tid & 31, wid = tid >> 5;
    const int g = lane >> 2, tg = lane & 3;
    const int wm = wid >> 1, wn = wid & 1;
    const int m0 = blockIdx.y * 128, n0 = blockIdx.x * 128;

    const uint32_t AsU = smem_u32(As), BsU = smem_u32(Bs);
    const int lr = tid >> 1;
    const int lsg = (tid & 1) * 8;

    const float* xrow = X + (long long)(m0 + lr) * D_ + lsg;
    const float* wrow = W + (long long)(n0 + lr) * D_ + lsg;
    const uint32_t adst = AsU + (uint32_t)(lr * 20 + lsg) * 4;
    const uint32_t bdst = BsU + (uint32_t)(lr * 20 + lsg) * 4;

#define G_ISSUE(s, kb)                                        \
    do {                                                      \
        const float* xs = xrow + (kb) * 16;                   \
        const float* ws = wrow + (kb) * 16;                   \
        const uint32_t so = (uint32_t)((s) * GSTG) * 4;       \
        cp_async16(adst + so, xs);                            \
        cp_async16(adst + so + 16, xs + 4);                   \
        cp_async16(bdst + so, ws);                            \
        cp_async16(bdst + so + 16, ws + 4);                   \
    } while (0)

    float acc[2][8][4];
#pragma unroll
    for (int mt = 0; mt < 2; mt++)
#pragma unroll
        for (int nt = 0; nt < 8; nt++)
#pragma unroll
            for (int i = 0; i < 4; i++) acc[mt][nt][i] = 0.0f;

    G_ISSUE(0, 0);
    CP_COMMIT();
    G_ISSUE(1, 1);
    CP_COMMIT();

    for (int it = 0; it < 64; it++) {
        CP_WAIT1();
        __syncthreads();
        int nx = it + 2;
        if (nx >= 64) nx -= 64;
        G_ISSUE((it + 2) % 3, nx);
        CP_COMMIT();

        const float* Ab = As + (it % 3) * GSTG;
        const float* Bb = Bs + (it % 3) * GSTG;
#pragma unroll
        for (int kk = 0; kk < 2; kk++) {
            const int kb = kk * 8 + tg;
            float a[2][4];
#pragma unroll
            for (int mt = 0; mt < 2; mt++) {
                const float* Ap = &Ab[(wm * 32 + mt * 16 + g) * 20 + kb];
                a[mt][0] = Ap[0];
                a[mt][2] = Ap[4];
                a[mt][1] = Ap[8 * 20];
                a[mt][3] = Ap[8 * 20 + 4];
            }
#pragma unroll
            for (int nt = 0; nt < 8; nt++) {
                const float* Bp = &Bb[(wn * 64 + nt * 8 + g) * 20 + kb];
                const float b0 = Bp[0], b1 = Bp[4];
                mma8(acc[0][nt], a[0][0], a[0][1], a[0][2], a[0][3], b0, b1);
                mma8(acc[1][nt], a[1][0], a[1][1], a[1][2], a[1][3], b0, b1);
            }
        }
    }
#undef G_ISSUE

#pragma unroll
    for (int mt = 0; mt < 2; mt++) {
        const int r0 = m0 + wm * 32 + mt * 16 + g;
#pragma unroll
        for (int nt = 0; nt < 8; nt++) {
            const int c = n0 + wn * 64 + nt * 8 + tg * 2;
            const float bv0 = bias[c], bv1 = bias[c + 1];
            float v00 = acc[mt][nt][0] + bv0, v01 = acc[mt][nt][1] + bv1;
            float v10 = acc[mt][nt][2] + bv0, v11 = acc[mt][nt][3] + bv1;
            if (SPLIT) {
                v00 = to_tf32(v00 * scale); v01 = to_tf32(v01 * scale);
                v10 = to_tf32(v10 * scale); v11 = to_tf32(v11 * scale);
                const int h = c >> 6, dk = c & 63;
                const int bb = r0 >> 11, ss = r0 & 2047;
                float* o0 = &out[(((bb * H_ + h) * S_) + ss) * DK_ + dk];
                *(float2*)o0 = make_float2(v00, v01);
                *(float2*)(o0 + 8 * DK_) = make_float2(v10, v11);
            } else {
                *(float2*)&out[r0 * D_ + c] = make_float2(v00, v01);
                *(float2*)&out[(r0 + 8) * D_ + c] = make_float2(v10, v11);
            }
        }
    }
}

// 0.125 * log2(e)
#define QSCALE 0.1803368801111204f

__global__ __launch_bounds__(256, 2) void qkv_kernel(
    const float* __restrict__ bq, const float* __restrict__ bk,
    const float* __restrict__ bv)
{
    extern __shared__ __align__(16) float sm[];
    float* As = sm;
    float* Bs = sm + 3 * GSTG;
    if (blockIdx.z == 0)      gemm_tc<true>(As, Bs, g_rq, g_rwq, bq, g_q, QSCALE);
    else if (blockIdx.z == 1) gemm_tc<true>(As, Bs, g_rk, g_rwk, bk, g_k, 1.0f);
    else                      gemm_tc<true>(As, Bs, g_rv, g_rwv, bv, g_v, 1.0f);
}

__global__ __launch_bounds__(256, 2) void oproj_kernel(
    const float* __restrict__ bo, float* __restrict__ out)
{
    extern __shared__ __align__(16) float sm[];
    float* As = sm;
    float* Bs = sm + 3 * GSTG;
    gemm_tc<false>(As, Bs, g_x, g_rwo, bo, out, 1.0f);
}

// ---------------------------------------------------------------------------
// Flash attention, Br=256 (warp owns 32 q-rows), Q and P in registers,
// XOR-swizzled stride-64 K/V smem (64KB), double-buffered cp.async,
// base-2 softmax.
// ---------------------------------------------------------------------------
#define ATKV (64 * 64)
#define ATTN_SMEM_BYTES (4 * ATKV * 4)   // 65536 B

__global__ __launch_bounds__(256) void attn_kernel(const int* __restrict__ mask)
{
    extern __shared__ __align__(16) float sm[];
    float* Ks = sm;                  // 2 stages
    float* Vt = sm + 2 * ATKV;       // 2 stages (dk rows x kv cols)

    const int tid = threadIdx.x;
    const int lane = tid & 31, wid = tid >> 5;
    const int g = lane >> 2, tg = lane & 3;
    const int w32 = wid * 32;
    const int q0 = blockIdx.x * 256;
    const int bh = blockIdx.y;

    const float* Qg = g_q + bh * S_ * DK_;
    const float* Kg = g_k + bh * S_ * DK_;
    const float* Vg = g_vT + bh * DK_ * S_;

    const uint32_t KsU = smem_u32(Ks), VtU = smem_u32(Vt);
    const int r = tid >> 2, qd = tid & 3;
    const int rsw = (r & 7) * 8;

#define KV_ISSUE(s, t)                                                          \
    do {                                                                        \
        const float* ksrc = Kg + ((t) * 64 + r) * DK_ + qd * 16;                \
        const float* vsrc = Vg + r * S_ + (t) * 64 + qd * 16;                   \
        const uint32_t kdb = KsU + (uint32_t)((s) * ATKV + r * 64) * 4;         \
        const uint32_t vdb = VtU + (uint32_t)((s) * ATKV + r * 64) * 4;         \
        _Pragma("unroll")                                                       \
        for (int j = 0; j < 4; j++) {                                           \
            const uint32_t co = (uint32_t)((qd * 16 + j * 4) ^ rsw) * 4;        \
            cp_async16(kdb + co, ksrc + j * 4);                                 \
            cp_async16(vdb + co, vsrc + j * 4);                                 \
        }                                                                       \
    } while (0)

    KV_ISSUE(0, 0);
    CP_COMMIT();
    KV_ISSUE(1, 1);
    CP_COMMIT();

    // Q fragments in registers: rows q0+w32+mt*16+g (A) / +8 (B), cols kk*8+tg*2
    float2 qA[2][8], qB[2][8];
#pragma unroll
    for (int mt = 0; mt < 2; mt++) {
        const float* qlo = Qg + (q0 + w32 + mt * 16 + g) * DK_ + tg * 2;
        const float* qhi = qlo + 8 * DK_;
#pragma unroll
        for (int kk = 0; kk < 8; kk++) {
            qA[mt][kk] = *(const float2*)(qlo + kk * 8);
            qB[mt][kk] = *(const float2*)(qhi + kk * 8);
        }
    }

    float mr[2][2], lr2[2][2];
#pragma unroll
    for (int mt = 0; mt < 2; mt++) {
        mr[mt][0] = -1e30f; mr[mt][1] = -1e30f;
        lr2[mt][0] = 0.0f;  lr2[mt][1] = 0.0f;
    }
    float o[2][8][4];
#pragma unroll
    for (int mt = 0; mt < 2; mt++)
#pragma unroll
        for (int nt = 0; nt < 8; nt++)
#pragma unroll
            for (int i = 0; i < 4; i++) o[mt][nt][i] = 0.0f;

    const int mrow = blockIdx.x * 2;   // 128-row mask-flag base

    for (int kt = 0; kt < 32; kt++) {
        CP_WAIT1();
        __syncthreads();
        const float* Ksb = Ks + (kt & 1) * ATKV;
        const float* Vtb = Vt + (kt & 1) * ATKV;

        // S = Q @ K^T (warp: 32x64), Q from registers
        float s[2][8][4];
#pragma unroll
        for (int mt = 0; mt < 2; mt++)
#pragma unroll
            for (int nt = 0; nt < 8; nt++)
#pragma unroll
                for (int i = 0; i < 4; i++) s[mt][nt][i] = 0.0f;

#pragma unroll
        for (int kk = 0; kk < 8; kk++) {
            const int fo = 8 * (kk ^ g) + tg * 2;
#pragma unroll
            for (int nt = 0; nt < 8; nt++) {
                const float2 bv = *(const float2*)&Ksb[(nt * 8 + g) * 64 + fo];
                mma8(s[0][nt], qA[0][kk].x, qB[0][kk].x, qA[0][kk].y, qB[0][kk].y,
                     bv.x, bv.y);
                mma8(s[1][nt], qA[1][kk].x, qB[1][kk].x, qA[1][kk].y, qB[1][kk].y,
                     bv.x, bv.y);
            }
        }

        // Mask (rare path; AND of the two 128-row flags covering this CTA)
        if (!(g_mflag[mrow * 32 + kt] & g_mflag[(mrow + 1) * 32 + kt])) {
            const int k0 = kt * 64;
#pragma unroll
            for (int mt = 0; mt < 2; mt++) {
                const int* mp0 = mask + (q0 + w32 + mt * 16 + g) * S_ + k0 + tg * 2;
                const int* mp1 = mp0 + 8 * S_;
#pragma unroll
                for (int nt = 0; nt < 8; nt++) {
                    const int2 m0v = *(const int2*)(mp0 + nt * 8);
                    const int2 m1v = *(const int2*)(mp1 + nt * 8);
                    if (m0v.x == 0) s[mt][nt][0] = -1e9f;
                    if (m0v.y == 0) s[mt][nt][1] = -1e9f;
                    if (m1v.x == 0) s[mt][nt][2] = -1e9f;
                    if (m1v.y == 0) s[mt][nt][3] = -1e9f;
                }
            }
        }

        // Online softmax (base 2); P stays in registers (s[])
#pragma unroll
        for (int mt = 0; mt < 2; mt++) {
            float mx0 = -1e30f, mx1 = -1e30f;
#pragma unroll
            for (int nt = 0; nt < 8; nt++) {
                mx0 = fmaxf(mx0, fmaxf(s[mt][nt][0], s[mt][nt][1]));
                mx1 = fmaxf(mx1, fmaxf(s[mt][nt][2], s[mt][nt][3]));
            }
            mx0 = fmaxf(mx0, __shfl_xor_sync(0xffffffffu, mx0, 1));
            mx0 = fmaxf(mx0, __shfl_xor_sync(0xffffffffu, mx0, 2));
            mx1 = fmaxf(mx1, __shfl_xor_sync(0xffffffffu, mx1, 1));
            mx1 = fmaxf(mx1, __shfl_xor_sync(0xffffffffu, mx1, 2));
            const float mn0 = fmaxf(mr[mt][0], mx0);
            const float mn1 = fmaxf(mr[mt][1], mx1);
            const float al0 = exp2f(mr[mt][0] - mn0);
            const float al1 = exp2f(mr[mt][1] - mn1);
            mr[mt][0] = mn0; mr[mt][1] = mn1;

            float sum0 = 0.0f, sum1 = 0.0f;
#pragma unroll
            for (int nt = 0; nt < 8; nt++) {
                const float p0 = exp2f(s[mt][nt][0] - mn0);
                const float p1 = exp2f(s[mt][nt][1] - mn0);
                const float p2 = exp2f(s[mt][nt][2] - mn1);
                const float p3 = exp2f(s[mt][nt][3] - mn1);
                sum0 += p0 + p1;
                sum1 += p2 + p3;
                s[mt][nt][0] = to_tf32(p0);
                s[mt][nt][1] = to_tf32(p1);
                s[mt][nt][2] = to_tf32(p2);
                s[mt][nt][3] = to_tf32(p3);
                o[mt][nt][0] *= al0; o[mt][nt][1] *= al0;
                o[mt][nt][2] *= al1; o[mt][nt][3] *= al1;
            }
            sum0 += __shfl_xor_sync(0xffffffffu, sum0, 1);
            sum0 += __shfl_xor_sync(0xffffffffu, sum0, 2);
            sum1 += __shfl_xor_sync(0xffffffffu, sum1, 1);
            sum1 += __shfl_xor_sync(0xffffffffu, sum1, 2);
            lr2[mt][0] = lr2[mt][0] * al0 + sum0;
            lr2[mt][1] = lr2[mt][1] * al1 + sum1;
        }

        // O += P @ V (one V B-frag load serves both m-tiles)
#pragma unroll
        for (int kk = 0; kk < 8; kk++) {
            const int fo = 8 * (kk ^ g) + tg * 2;
#pragma unroll
            for (int nt = 0; nt < 8; nt++) {
                const float2 bv = *(const float2*)&Vtb[(nt * 8 + g) * 64 + fo];
                mma8(o[0][nt], s[0][kk][0], s[0][kk][2], s[0][kk][1], s[0][kk][3],
                     bv.x, bv.y);
                mma8(o[1][nt], s[1][kk][0], s[1][kk][2], s[1][kk][1], s[1][kk][3],
                     bv.x, bv.y);
            }
        }

        __syncthreads();   // all warps done with stage (kt&1)
        KV_ISSUE(kt & 1, (kt + 2) & 31);   // wrap: last 2 iters load dead data
        CP_COMMIT();
    }
#undef KV_ISSUE

    CP_WAIT0();  // drain async copies before CTA exit

    // Normalize, round to tf32 (consumed via cp.async by oproj), store [B,S,D]
    const int bb = bh >> 4, h = bh & 15;
#pragma unroll
    for (int mt = 0; mt < 2; mt++) {
        const float inv0 = 1.0f / lr2[mt][0];
        const float inv1 = 1.0f / lr2[mt][1];
        const int r0 = q0 + w32 + mt * 16 + g;
        float* O0 = &g_x[(bb * S_ + r0) * D_ + h * DK_ + tg * 2];
        float* O1 = O0 + 8 * D_;
#pragma unroll
        for (int nt = 0; nt < 8; nt++) {
            *(float2*)(O0 + nt * 8) =
                make_float2(to_tf32(o[mt][nt][0] * inv0), to_tf32(o[mt][nt][1] * inv0));
            *(float2*)(O1 + nt * 8) =
                make_float2(to_tf32(o[mt][nt][2] * inv1), to_tf32(o[mt][nt][3] * inv1));
        }
    }
}

// ---------------------------------------------------------------------------
extern "C" void kernel_launch(void* const* d_in, const int* in_sizes, int n_in,
                              void* d_out, int out_size)
{
    (void)in_sizes; (void)n_in; (void)out_size;
    const float* q    = (const float*)d_in[0];
    const float* k    = (const float*)d_in[1];
    const float* v    = (const float*)d_in[2];
    const int*   mask = (const int*)d_in[3];
    const float* wq   = (const float*)d_in[4];
    const float* bq   = (const float*)d_in[5];
    const float* wk   = (const float*)d_in[6];
    const float* bk   = (const float*)d_in[7];
    const float* wv   = (const float*)d_in[8];
    const float* bv   = (const float*)d_in[9];
    const float* wo   = (const float*)d_in[10];
    const float* bo   = (const float*)d_in[11];
    float* out = (float*)d_out;

    static bool attrs_set = false;
    if (!attrs_set) {
        cudaFuncSetAttribute(qkv_kernel, cudaFuncAttributeMaxDynamicSharedMemorySize,
                             GEMM_SMEM_BYTES);
        cudaFuncSetAttribute(oproj_kernel, cudaFuncAttributeMaxDynamicSharedMemorySize,
                             GEMM_SMEM_BYTES);
        cudaFuncSetAttribute(attn_kernel, cudaFuncAttributeMaxDynamicSharedMemorySize,
                             ATTN_SMEM_BYTES);
        attrs_set = true;
    }

    // Fused prepass: tf32 rounding + mask prescan
    dim3 gpre(1024, 8);
    pre_kernel<<<gpre, 256>>>(q, k, v, wq, wk, wv, wo, mask);

    // QKV projections
    dim3 gqkv(D_ / 128, M_ / 128, 3);
    qkv_kernel<<<gqkv, 256, GEMM_SMEM_BYTES>>>(bq, bk, bv);

    // V transpose
    dim3 gvt(S_ / 32, DK_ / 32, B_ * H_);
    vtrans_kernel<<<gvt, 256>>>();

    // Attention (4th launch — ncu capture slot)
    dim3 gattn(S_ / 256, B_ * H_);
    attn_kernel<<<gattn, 256, ATTN_SMEM_BYTES>>>(mask);

    // Output projection
    dim3 gop(D_ / 128, M_ / 128);
    oproj_kernel<<<gop, 256, GEMM_SMEM_BYTES>>>(bo, out);
}

// round 9
// speedup vs baseline: 1.1530x; 1.0081x over previous
#include <cuda_runtime.h>
#include <cstdint>

#define B_ 4
#define S_ 2048
#define D_ 1024
#define H_ 16
#define DK_ 64
#define M_ (B_ * S_)   // 8192

// Scratch (device globals — no allocation allowed)
__device__ float g_q[M_ * D_];     // [B,H,S,DK] tf32, q pre-scaled by 0.125*log2e
__device__ float g_k[M_ * D_];     // [B,H,S,DK] tf32
__device__ float g_vT[M_ * D_];    // [B,H,DK,S] tf32 (V projected + transposed)
__device__ float g_x[M_ * D_];     // [B,S,D] attention out, tf32-rounded
__device__ float g_rq[M_ * D_];    // tf32-rounded copies of raw inputs
__device__ float g_rk[M_ * D_];
__device__ float g_rv[M_ * D_];
__device__ float g_rwq[D_ * D_];
__device__ float g_rwk[D_ * D_];
__device__ float g_rwv[D_ * D_];
__device__ float g_rwo[D_ * D_];
__device__ int   g_mflag[16 * 32];

__device__ __forceinline__ float to_tf32(float x) {
    float r;
    asm("cvt.rna.tf32.f32 %0, %1;" : "=f"(r) : "f"(x));
    return r;
}

__device__ __forceinline__ void mma8(float c[4], float a0, float a1, float a2, float a3,
                                     float b0, float b1) {
    asm volatile(
        "mma.sync.aligned.m16n8k8.row.col.f32.tf32.tf32.f32 "
        "{%0,%1,%2,%3}, {%4,%5,%6,%7}, {%8,%9}, {%0,%1,%2,%3};"
        : "+f"(c[0]), "+f"(c[1]), "+f"(c[2]), "+f"(c[3])
        : "r"(__float_as_uint(a0)), "r"(__float_as_uint(a1)),
          "r"(__float_as_uint(a2)), "r"(__float_as_uint(a3)),
          "r"(__float_as_uint(b0)), "r"(__float_as_uint(b1)));
}

__device__ __forceinline__ uint32_t smem_u32(const void* p) {
    return (uint32_t)__cvta_generic_to_shared(p);
}
__device__ __forceinline__ void cp_async16(uint32_t dst, const float* src) {
    asm volatile("cp.async.ca.shared.global [%0], [%1], 16;" :: "r"(dst), "l"(src));
}
#define CP_COMMIT() asm volatile("cp.async.commit_group;")
#define CP_WAIT1()  asm volatile("cp.async.wait_group 1;")
#define CP_WAIT0()  asm volatile("cp.async.wait_group 0;")

// ---------------------------------------------------------------------------
// Prepass kernels (split so qkv lands on the ncu capture slot)
// ---------------------------------------------------------------------------
__global__ __launch_bounds__(256) void pre_act_kernel(
    const float* __restrict__ q, const float* __restrict__ k, const float* __restrict__ v)
{
    const int which = blockIdx.y;
    const float* src = (which == 0) ? q : (which == 1) ? k : v;
    float* dst = (which == 0) ? g_rq : (which == 1) ? g_rk : g_rv;
    const int n4 = M_ * D_ / 4;
    const int stride = gridDim.x * blockDim.x;
    for (int i = blockIdx.x * blockDim.x + threadIdx.x; i < n4; i += stride) {
        float4 t = ((const float4*)src)[i];
        ((float4*)dst)[i] =
            make_float4(to_tf32(t.x), to_tf32(t.y), to_tf32(t.z), to_tf32(t.w));
    }
}

__global__ __launch_bounds__(256) void pre_w_kernel(
    const float* __restrict__ wq, const float* __restrict__ wk,
    const float* __restrict__ wv, const float* __restrict__ wo)
{
    const int which = blockIdx.y;
    const float* src = (which == 0) ? wq : (which == 1) ? wk : (which == 2) ? wv : wo;
    float* dst = (which == 0) ? g_rwq : (which == 1) ? g_rwk : (which == 2) ? g_rwv : g_rwo;
    const int n4 = D_ * D_ / 4;
    const int stride = gridDim.x * blockDim.x;
    for (int i = blockIdx.x * blockDim.x + threadIdx.x; i < n4; i += stride) {
        float4 t = ((const float4*)src)[i];
        ((float4*)dst)[i] =
            make_float4(to_tf32(t.x), to_tf32(t.y), to_tf32(t.z), to_tf32(t.w));
    }
}

__global__ __launch_bounds__(256) void pre_mask_kernel(const int* __restrict__ mask)
{
    const int qt = blockIdx.x >> 5, kt = blockIdx.x & 31;
    const int tid = threadIdx.x;
    const int r = tid >> 1, h = tid & 1;
    const int* p = mask + (qt * 128 + r) * S_ + kt * 64 + h * 32;
    bool ok = true;
#pragma unroll
    for (int j = 0; j < 8; j++) {
        int4 mv = *(const int4*)(p + j * 4);
        ok &= (mv.x != 0) & (mv.y != 0) & (mv.z != 0) & (mv.w != 0);
    }
    const int all = __syncthreads_and((int)ok);
    if (tid == 0) g_mflag[qt * 32 + kt] = all;
}

// ---------------------------------------------------------------------------
// tf32 tensor-core GEMM, 3-stage cp.async pipeline.
// MODE 0: out [M,D]; MODE 1: head-split [B,H,S,DK]; MODE 2: split+transposed
// [B,H,DK,S] (V path — fuses the old vtrans kernel).
// ---------------------------------------------------------------------------
#define GSTG 2560              // 128*20 floats per stage per tensor
#define GEMM_SMEM_BYTES (2 * 3 * GSTG * 4)

template <int MODE>
__device__ __forceinline__ void gemm_tc(
    float* As, float* Bs,
    const float* __restrict__ X, const float* __restrict__ W,
    const float* __restrict__ bias, float* __restrict__ out, float scale)
{
    const int tid = threadIdx.x;
    const int lane = tid & 31, wid = tid >> 5;
    const int g = lane >> 2, tg = lane & 3;
    const int wm = wid >> 1, wn = wid & 1;
    const int m0 = blockIdx.y * 128, n0 = blockIdx.x * 128;

    const uint32_t AsU = smem_u32(As), BsU = smem_u32(Bs);
    const int lr = tid >> 1;
    const int lsg = (tid & 1) * 8;

    const float* xrow = X + (long long)(m0 + lr) * D_ + lsg;
    const float* wrow = W + (long long)(n0 + lr) * D_ + lsg;
    const uint32_t adst = AsU + (uint32_t)(lr * 20 + lsg) * 4;
    const uint32_t bdst = BsU + (uint32_t)(lr * 20 + lsg) * 4;

#define G_ISSUE(s, kb)                                        \
    do {                                                      \
        const float* xs = xrow + (kb) * 16;                   \
        const float* ws = wrow + (kb) * 16;                   \
        const uint32_t so = (uint32_t)((s) * GSTG) * 4;       \
        cp_async16(adst + so, xs);                            \
        cp_async16(adst + so + 16, xs + 4);                   \
        cp_async16(bdst + so, ws);                            \
        cp_async16(bdst + so + 16, ws + 4);                   \
    } while (0)

    float acc[2][8][4];
#pragma unroll
    for (int mt = 0; mt < 2; mt++)
#pragma unroll
        for (int nt = 0; nt < 8; nt++)
#pragma unroll
            for (int i = 0; i < 4; i++) acc[mt][nt][i] = 0.0f;

    G_ISSUE(0, 0);
    CP_COMMIT();
    G_ISSUE(1, 1);
    CP_COMMIT();

    for (int it = 0; it < 64; it++) {
        CP_WAIT1();
        __syncthreads();
        int nx = it + 2;
        if (nx >= 64) nx -= 64;
        G_ISSUE((it + 2) % 3, nx);
        CP_COMMIT();

        const float* Ab = As + (it % 3) * GSTG;
        const float* Bb = Bs + (it % 3) * GSTG;
#pragma unroll
        for (int kk = 0; kk < 2; kk++) {
            const int kb = kk * 8 + tg;
            float a[2][4];
#pragma unroll
            for (int mt = 0; mt < 2; mt++) {
                const float* Ap = &Ab[(wm * 32 + mt * 16 + g) * 20 + kb];
                a[mt][0] = Ap[0];
                a[mt][2] = Ap[4];
                a[mt][1] = Ap[8 * 20];
                a[mt][3] = Ap[8 * 20 + 4];
            }
#pragma unroll
            for (int nt = 0; nt < 8; nt++) {
                const float* Bp = &Bb[(wn * 64 + nt * 8 + g) * 20 + kb];
                const float b0 = Bp[0], b1 = Bp[4];
                mma8(acc[0][nt], a[0][0], a[0][1], a[0][2], a[0][3], b0, b1);
                mma8(acc[1][nt], a[1][0], a[1][1], a[1][2], a[1][3], b0, b1);
            }
        }
    }
#undef G_ISSUE

#pragma unroll
    for (int mt = 0; mt < 2; mt++) {
        const int r0 = m0 + wm * 32 + mt * 16 + g;
#pragma unroll
        for (int nt = 0; nt < 8; nt++) {
            const int c = n0 + wn * 64 + nt * 8 + tg * 2;
            const float bv0 = bias[c], bv1 = bias[c + 1];
            float v00 = acc[mt][nt][0] + bv0, v01 = acc[mt][nt][1] + bv1;
            float v10 = acc[mt][nt][2] + bv0, v11 = acc[mt][nt][3] + bv1;
            if (MODE >= 1) {
                v00 = to_tf32(v00 * scale); v01 = to_tf32(v01 * scale);
                v10 = to_tf32(v10 * scale); v11 = to_tf32(v11 * scale);
                const int h = c >> 6, dk = c & 63;
                const int bb = r0 >> 11, ss = r0 & 2047;
                if (MODE == 1) {
                    float* o0 = &out[(((bb * H_ + h) * S_) + ss) * DK_ + dk];
                    *(float2*)o0 = make_float2(v00, v01);
                    *(float2*)(o0 + 8 * DK_) = make_float2(v10, v11);
                } else {
                    // MODE 2: transposed store [B,H,DK,S]
                    float* o0 = &out[(((bb * H_ + h) * DK_) + dk) * S_ + ss];
                    o0[0] = v00;
                    o0[8] = v10;
                    o0[S_] = v01;
                    o0[S_ + 8] = v11;
                }
            } else {
                *(float2*)&out[r0 * D_ + c] = make_float2(v00, v01);
                *(float2*)&out[(r0 + 8) * D_ + c] = make_float2(v10, v11);
            }
        }
    }
}

// 0.125 * log2(e)
#define QSCALE 0.1803368801111204f

__global__ __launch_bounds__(256, 2) void qkv_kernel(
    const float* __restrict__ bq, const float* __restrict__ bk,
    const float* __restrict__ bv)
{
    extern __shared__ __align__(16) float sm[];
    float* As = sm;
    float* Bs = sm + 3 * GSTG;
    if (blockIdx.z == 0)      gemm_tc<1>(As, Bs, g_rq, g_rwq, bq, g_q, QSCALE);
    else if (blockIdx.z == 1) gemm_tc<1>(As, Bs, g_rk, g_rwk, bk, g_k, 1.0f);
    else                      gemm_tc<2>(As, Bs, g_rv, g_rwv, bv, g_vT, 1.0f);
}

__global__ __launch_bounds__(256, 2) void oproj_kernel(
    const float* __restrict__ bo, float* __restrict__ out)
{
    extern __shared__ __align__(16) float sm[];
    float* As = sm;
    float* Bs = sm + 3 * GSTG;
    gemm_tc<0>(As, Bs, g_x, g_rwo, bo, out, 1.0f);
}

// ---------------------------------------------------------------------------
// Flash attention, Br=256 (warp owns 32 q-rows), Q and P in registers,
// XOR-swizzled stride-64 K/V smem (64KB), double-buffered cp.async,
// base-2 softmax. (unchanged from R8)
// ---------------------------------------------------------------------------
#define ATKV (64 * 64)
#define ATTN_SMEM_BYTES (4 * ATKV * 4)   // 65536 B

__global__ __launch_bounds__(256) void attn_kernel(const int* __restrict__ mask)
{
    extern __shared__ __align__(16) float sm[];
    float* Ks = sm;                  // 2 stages
    float* Vt = sm + 2 * ATKV;       // 2 stages (dk rows x kv cols)

    const int tid = threadIdx.x;
    const int lane = tid & 31, wid = tid >> 5;
    const int g = lane >> 2, tg = lane & 3;
    const int w32 = wid * 32;
    const int q0 = blockIdx.x * 256;
    const int bh = blockIdx.y;

    const float* Qg = g_q + bh * S_ * DK_;
    const float* Kg = g_k + bh * S_ * DK_;
    const float* Vg = g_vT + bh * DK_ * S_;

    const uint32_t KsU = smem_u32(Ks), VtU = smem_u32(Vt);
    const int r = tid >> 2, qd = tid & 3;
    const int rsw = (r & 7) * 8;

#define KV_ISSUE(s, t)                                                          \
    do {                                                                        \
        const float* ksrc = Kg + ((t) * 64 + r) * DK_ + qd * 16;                \
        const float* vsrc = Vg + r * S_ + (t) * 64 + qd * 16;                   \
        const uint32_t kdb = KsU + (uint32_t)((s) * ATKV + r * 64) * 4;         \
        const uint32_t vdb = VtU + (uint32_t)((s) * ATKV + r * 64) * 4;         \
        _Pragma("unroll")                                                       \
        for (int j = 0; j < 4; j++) {                                           \
            const uint32_t co = (uint32_t)((qd * 16 + j * 4) ^ rsw) * 4;        \
            cp_async16(kdb + co, ksrc + j * 4);                                 \
            cp_async16(vdb + co, vsrc + j * 4);                                 \
        }                                                                       \
    } while (0)

    KV_ISSUE(0, 0);
    CP_COMMIT();
    KV_ISSUE(1, 1);
    CP_COMMIT();

    // Q fragments in registers
    float2 qA[2][8], qB[2][8];
#pragma unroll
    for (int mt = 0; mt < 2; mt++) {
        const float* qlo = Qg + (q0 + w32 + mt * 16 + g) * DK_ + tg * 2;
        const float* qhi = qlo + 8 * DK_;
#pragma unroll
        for (int kk = 0; kk < 8; kk++) {
            qA[mt][kk] = *(const float2*)(qlo + kk * 8);
            qB[mt][kk] = *(const float2*)(qhi + kk * 8);
        }
    }

    float mr[2][2], lr2[2][2];
#pragma unroll
    for (int mt = 0; mt < 2; mt++) {
        mr[mt][0] = -1e30f; mr[mt][1] = -1e30f;
        lr2[mt][0] = 0.0f;  lr2[mt][1] = 0.0f;
    }
    float o[2][8][4];
#pragma unroll
    for (int mt = 0; mt < 2; mt++)
#pragma unroll
        for (int nt = 0; nt < 8; nt++)
#pragma unroll
            for (int i = 0; i < 4; i++) o[mt][nt][i] = 0.0f;

    const int mrow = blockIdx.x * 2;

    for (int kt = 0; kt < 32; kt++) {
        CP_WAIT1();
        __syncthreads();
        const float* Ksb = Ks + (kt & 1) * ATKV;
        const float* Vtb = Vt + (kt & 1) * ATKV;

        float s[2][8][4];
#pragma unroll
        for (int mt = 0; mt < 2; mt++)
#pragma unroll
            for (int nt = 0; nt < 8; nt++)
#pragma unroll
                for (int i = 0; i < 4; i++) s[mt][nt][i] = 0.0f;

#pragma unroll
        for (int kk = 0; kk < 8; kk++) {
            const int fo = 8 * (kk ^ g) + tg * 2;
#pragma unroll
            for (int nt = 0; nt < 8; nt++) {
                const float2 bv = *(const float2*)&Ksb[(nt * 8 + g) * 64 + fo];
                mma8(s[0][nt], qA[0][kk].x, qB[0][kk].x, qA[0][kk].y, qB[0][kk].y,
                     bv.x, bv.y);
                mma8(s[1][nt], qA[1][kk].x, qB[1][kk].x, qA[1][kk].y, qB[1][kk].y,
                     bv.x, bv.y);
            }
        }

        if (!(g_mflag[mrow * 32 + kt] & g_mflag[(mrow + 1) * 32 + kt])) {
            const int k0 = kt * 64;
#pragma unroll
            for (int mt = 0; mt < 2; mt++) {
                const int* mp0 = mask + (q0 + w32 + mt * 16 + g) * S_ + k0 + tg * 2;
                const int* mp1 = mp0 + 8 * S_;
#pragma unroll
                for (int nt = 0; nt < 8; nt++) {
                    const int2 m0v = *(const int2*)(mp0 + nt * 8);
                    const int2 m1v = *(const int2*)(mp1 + nt * 8);
                    if (m0v.x == 0) s[mt][nt][0] = -1e9f;
                    if (m0v.y == 0) s[mt][nt][1] = -1e9f;
                    if (m1v.x == 0) s[mt][nt][2] = -1e9f;
                    if (m1v.y == 0) s[mt][nt][3] = -1e9f;
                }
            }
        }

#pragma unroll
        for (int mt = 0; mt < 2; mt++) {
            float mx0 = -1e30f, mx1 = -1e30f;
#pragma unroll
            for (int nt = 0; nt < 8; nt++) {
                mx0 = fmaxf(mx0, fmaxf(s[mt][nt][0], s[mt][nt][1]));
                mx1 = fmaxf(mx1, fmaxf(s[mt][nt][2], s[mt][nt][3]));
            }
            mx0 = fmaxf(mx0, __shfl_xor_sync(0xffffffffu, mx0, 1));
            mx0 = fmaxf(mx0, __shfl_xor_sync(0xffffffffu, mx0, 2));
            mx1 = fmaxf(mx1, __shfl_xor_sync(0xffffffffu, mx1, 1));
            mx1 = fmaxf(mx1, __shfl_xor_sync(0xffffffffu, mx1, 2));
            const float mn0 = fmaxf(mr[mt][0], mx0);
            const float mn1 = fmaxf(mr[mt][1], mx1);
            const float al0 = exp2f(mr[mt][0] - mn0);
            const float al1 = exp2f(mr[mt][1] - mn1);
            mr[mt][0] = mn0; mr[mt][1] = mn1;

            float sum0 = 0.0f, sum1 = 0.0f;
#pragma unroll
            for (int nt = 0; nt < 8; nt++) {
                const float p0 = exp2f(s[mt][nt][0] - mn0);
                const float p1 = exp2f(s[mt][nt][1] - mn0);
                const float p2 = exp2f(s[mt][nt][2] - mn1);
                const float p3 = exp2f(s[mt][nt][3] - mn1);
                sum0 += p0 + p1;
                sum1 += p2 + p3;
                s[mt][nt][0] = to_tf32(p0);
                s[mt][nt][1] = to_tf32(p1);
                s[mt][nt][2] = to_tf32(p2);
                s[mt][nt][3] = to_tf32(p3);
                o[mt][nt][0] *= al0; o[mt][nt][1] *= al0;
                o[mt][nt][2] *= al1; o[mt][nt][3] *= al1;
            }
            sum0 += __shfl_xor_sync(0xffffffffu, sum0, 1);
            sum0 += __shfl_xor_sync(0xffffffffu, sum0, 2);
            sum1 += __shfl_xor_sync(0xffffffffu, sum1, 1);
            sum1 += __shfl_xor_sync(0xffffffffu, sum1, 2);
            lr2[mt][0] = lr2[mt][0] * al0 + sum0;
            lr2[mt][1] = lr2[mt][1] * al1 + sum1;
        }

#pragma unroll
        for (int kk = 0; kk < 8; kk++) {
            const int fo = 8 * (kk ^ g) + tg * 2;
#pragma unroll
            for (int nt = 0; nt < 8; nt++) {
                const float2 bv = *(const float2*)&Vtb[(nt * 8 + g) * 64 + fo];
                mma8(o[0][nt], s[0][kk][0], s[0][kk][2], s[0][kk][1], s[0][kk][3],
                     bv.x, bv.y);
                mma8(o[1][nt], s[1][kk][0], s[1][kk][2], s[1][kk][1], s[1][kk][3],
                     bv.x, bv.y);
            }
        }

        __syncthreads();
        KV_ISSUE(kt & 1, (kt + 2) & 31);
        CP_COMMIT();
    }
#undef KV_ISSUE

    CP_WAIT0();

    const int bb = bh >> 4, h = bh & 15;
#pragma unroll
    for (int mt = 0; mt < 2; mt++) {
        const float inv0 = 1.0f / lr2[mt][0];
        const float inv1 = 1.0f / lr2[mt][1];
        const int r0 = q0 + w32 + mt * 16 + g;
        float* O0 = &g_x[(bb * S_ + r0) * D_ + h * DK_ + tg * 2];
        float* O1 = O0 + 8 * D_;
#pragma unroll
        for (int nt = 0; nt < 8; nt++) {
            *(float2*)(O0 + nt * 8) =
                make_float2(to_tf32(o[mt][nt][0] * inv0), to_tf32(o[mt][nt][1] * inv0));
            *(float2*)(O1 + nt * 8) =
                make_float2(to_tf32(o[mt][nt][2] * inv1), to_tf32(o[mt][nt][3] * inv1));
        }
    }
}

// ---------------------------------------------------------------------------
extern "C" void kernel_launch(void* const* d_in, const int* in_sizes, int n_in,
                              void* d_out, int out_size)
{
    (void)in_sizes; (void)n_in; (void)out_size;
    const float* q    = (const float*)d_in[0];
    const float* k    = (const float*)d_in[1];
    const float* v    = (const float*)d_in[2];
    const int*   mask = (const int*)d_in[3];
    const float* wq   = (const float*)d_in[4];
    const float* bq   = (const float*)d_in[5];
    const float* wk   = (const float*)d_in[6];
    const float* bk   = (const float*)d_in[7];
    const float* wv   = (const float*)d_in[8];
    const float* bv   = (const float*)d_in[9];
    const float* wo   = (const float*)d_in[10];
    const float* bo   = (const float*)d_in[11];
    float* out = (float*)d_out;

    static bool attrs_set = false;
    if (!attrs_set) {
        cudaFuncSetAttribute(qkv_kernel, cudaFuncAttributeMaxDynamicSharedMemorySize,
                             GEMM_SMEM_BYTES);
        cudaFuncSetAttribute(oproj_kernel, cudaFuncAttributeMaxDynamicSharedMemorySize,
                             GEMM_SMEM_BYTES);
        cudaFuncSetAttribute(attn_kernel, cudaFuncAttributeMaxDynamicSharedMemorySize,
                             ATTN_SMEM_BYTES);
        attrs_set = true;
    }

    // Prepass (3 launches so qkv is the 4th = ncu capture slot)
    dim3 ga(512, 3);
    pre_act_kernel<<<ga, 256>>>(q, k, v);
    dim3 gw(256, 4);
    pre_w_kernel<<<gw, 256>>>(wq, wk, wv, wo);
    pre_mask_kernel<<<512, 256>>>(mask);

    // QKV projections (V writes g_vT directly — vtrans fused)
    dim3 gqkv(D_ / 128, M_ / 128, 3);
    qkv_kernel<<<gqkv, 256, GEMM_SMEM_BYTES>>>(bq, bk, bv);

    // Attention
    dim3 gattn(S_ / 256, B_ * H_);
    attn_kernel<<<gattn, 256, ATTN_SMEM_BYTES>>>(mask);

    // Output projection
    dim3 gop(D_ / 128, M_ / 128);
    oproj_kernel<<<gop, 256, GEMM_SMEM_BYTES>>>(bo, out);
}

// round 10
// speedup vs baseline: 1.2204x; 1.0585x over previous
#include <cuda_runtime.h>
#include <cstdint>

#define B_ 4
#define S_ 2048
#define D_ 1024
#define H_ 16
#define DK_ 64
#define M_ (B_ * S_)   // 8192

__device__ float g_q[M_ * D_];     // [B,H,S,DK] tf32, q pre-scaled by 0.125*log2e
__device__ float g_k[M_ * D_];     // [B,H,S,DK] tf32
__device__ float g_vT[M_ * D_];    // [B,H,DK,S] tf32 (V projected + transposed)
__device__ float g_x[M_ * D_];     // [B,S,D] attention out, tf32-rounded
__device__ float g_rq[M_ * D_];
__device__ float g_rk[M_ * D_];
__device__ float g_rv[M_ * D_];
__device__ float g_rwq[D_ * D_];
__device__ float g_rwk[D_ * D_];
__device__ float g_rwv[D_ * D_];
__device__ float g_rwo[D_ * D_];
__device__ int   g_mflag[16 * 32];

__device__ __forceinline__ float to_tf32(float x) {
    float r;
    asm("cvt.rna.tf32.f32 %0, %1;" : "=f"(r) : "f"(x));
    return r;
}

__device__ __forceinline__ void mma8(float c[4], float a0, float a1, float a2, float a3,
                                     float b0, float b1) {
    asm volatile(
        "mma.sync.aligned.m16n8k8.row.col.f32.tf32.tf32.f32 "
        "{%0,%1,%2,%3}, {%4,%5,%6,%7}, {%8,%9}, {%0,%1,%2,%3};"
        : "+f"(c[0]), "+f"(c[1]), "+f"(c[2]), "+f"(c[3])
        : "r"(__float_as_uint(a0)), "r"(__float_as_uint(a1)),
          "r"(__float_as_uint(a2)), "r"(__float_as_uint(a3)),
          "r"(__float_as_uint(b0)), "r"(__float_as_uint(b1)));
}

__device__ __forceinline__ uint32_t smem_u32(const void* p) {
    return (uint32_t)__cvta_generic_to_shared(p);
}
__device__ __forceinline__ void cp_async16(uint32_t dst, const float* src) {
    asm volatile("cp.async.ca.shared.global [%0], [%1], 16;" :: "r"(dst), "l"(src));
}
#define CP_COMMIT() asm volatile("cp.async.commit_group;")
#define CP_WAIT1()  asm volatile("cp.async.wait_group 1;")
#define CP_WAIT0()  asm volatile("cp.async.wait_group 0;")

// ---------------------------------------------------------------------------
// Prepass kernels (split so qkv lands on the ncu capture slot)
// ---------------------------------------------------------------------------
__global__ __launch_bounds__(256) void pre_act_kernel(
    const float* __restrict__ q, const float* __restrict__ k, const float* __restrict__ v)
{
    const int which = blockIdx.y;
    const float* src = (which == 0) ? q : (which == 1) ? k : v;
    float* dst = (which == 0) ? g_rq : (which == 1) ? g_rk : g_rv;
    const int n4 = M_ * D_ / 4;
    const int stride = gridDim.x * blockDim.x;
    for (int i = blockIdx.x * blockDim.x + threadIdx.x; i < n4; i += stride) {
        float4 t = ((const float4*)src)[i];
        ((float4*)dst)[i] =
            make_float4(to_tf32(t.x), to_tf32(t.y), to_tf32(t.z), to_tf32(t.w));
    }
}

__global__ __launch_bounds__(256) void pre_w_kernel(
    const float* __restrict__ wq, const float* __restrict__ wk,
    const float* __restrict__ wv, const float* __restrict__ wo)
{
    const int which = blockIdx.y;
    const float* src = (which == 0) ? wq : (which == 1) ? wk : (which == 2) ? wv : wo;
    float* dst = (which == 0) ? g_rwq : (which == 1) ? g_rwk : (which == 2) ? g_rwv : g_rwo;
    const int n4 = D_ * D_ / 4;
    const int stride = gridDim.x * blockDim.x;
    for (int i = blockIdx.x * blockDim.x + threadIdx.x; i < n4; i += stride) {
        float4 t = ((const float4*)src)[i];
        ((float4*)dst)[i] =
            make_float4(to_tf32(t.x), to_tf32(t.y), to_tf32(t.z), to_tf32(t.w));
    }
}

__global__ __launch_bounds__(256) void pre_mask_kernel(const int* __restrict__ mask)
{
    const int qt = blockIdx.x >> 5, kt = blockIdx.x & 31;
    const int tid = threadIdx.x;
    const int r = tid >> 1, h = tid & 1;
    const int* p = mask + (qt * 128 + r) * S_ + kt * 64 + h * 32;
    bool ok = true;
#pragma unroll
    for (int j = 0; j < 8; j++) {
        int4 mv = *(const int4*)(p + j * 4);
        ok &= (mv.x != 0) & (mv.y != 0) & (mv.z != 0) & (mv.w != 0);
    }
    const int all = __syncthreads_and((int)ok);
    if (tid == 0) g_mflag[qt * 32 + kt] = all;
}

// ---------------------------------------------------------------------------
// tf32 tensor-core GEMM: BK=32 per stage, 2-stage double buffer, stride-40
// smem (conflict-free float2 fragments per 16-lane phase: 8g+2tg < 32),
// k-slot permutation applied to BOTH A and B fragments (dot preserved).
// MODE 0: out [M,D]; 1: head-split [B,H,S,DK]; 2: split+transposed [B,H,DK,S].
// ---------------------------------------------------------------------------
#define GST 40
#define GSTG2 (128 * GST)          // floats per stage per tensor
#define GEMM_SMEM_BYTES (2 * 2 * GSTG2 * 4)   // 81920 B

template <int MODE>
__device__ __forceinline__ void gemm_tc(
    float* As, float* Bs,
    const float* __restrict__ X, const float* __restrict__ W,
    const float* __restrict__ bias, float* __restrict__ out, float scale)
{
    const int tid = threadIdx.x;
    const int lane = tid & 31, wid = tid >> 5;
    const int g = lane >> 2, tg = lane & 3;
    const int wm = wid >> 1, wn = wid & 1;
    const int m0 = blockIdx.y * 128, n0 = blockIdx.x * 128;

    const uint32_t AsU = smem_u32(As), BsU = smem_u32(Bs);
    const int lr = tid >> 1;            // row 0..127
    const int lsg = (tid & 1) * 16;     // col 0 or 16

    const float* xrow = X + (long long)(m0 + lr) * D_ + lsg;
    const float* wrow = W + (long long)(n0 + lr) * D_ + lsg;
    const uint32_t adst = AsU + (uint32_t)(lr * GST + lsg) * 4;
    const uint32_t bdst = BsU + (uint32_t)(lr * GST + lsg) * 4;

#define G_ISSUE(s, kb)                                        \
    do {                                                      \
        const float* xs = xrow + (kb) * 32;                   \
        const float* ws = wrow + (kb) * 32;                   \
        const uint32_t so = (uint32_t)((s) * GSTG2) * 4;      \
        cp_async16(adst + so,      xs);                       \
        cp_async16(adst + so + 16, xs + 4);                   \
        cp_async16(adst + so + 32, xs + 8);                   \
        cp_async16(adst + so + 48, xs + 12);                  \
        cp_async16(bdst + so,      ws);                       \
        cp_async16(bdst + so + 16, ws + 4);                   \
        cp_async16(bdst + so + 32, ws + 8);                   \
        cp_async16(bdst + so + 48, ws + 12);                  \
    } while (0)

    float acc[2][8][4];
#pragma unroll
    for (int mt = 0; mt < 2; mt++)
#pragma unroll
        for (int nt = 0; nt < 8; nt++)
#pragma unroll
            for (int i = 0; i < 4; i++) acc[mt][nt][i] = 0.0f;

    G_ISSUE(0, 0);
    CP_COMMIT();

    for (int it = 0; it < 32; it++) {
        CP_WAIT0();
        __syncthreads();
        if (it < 31) {
            G_ISSUE((it + 1) & 1, it + 1);
            CP_COMMIT();
        }

        const float* Ab = As + (it & 1) * GSTG2;
        const float* Bb = Bs + (it & 1) * GSTG2;
#pragma unroll
        for (int kk = 0; kk < 4; kk++) {
            const int kc = kk * 8 + tg * 2;   // logical k cols 2tg,2tg+1 -> slots tg,tg+4
            float2 a0[2], a1[2];
#pragma unroll
            for (int mt = 0; mt < 2; mt++) {
                const int rb = wm * 32 + mt * 16 + g;
                a0[mt] = *(const float2*)&Ab[rb * GST + kc];
                a1[mt] = *(const float2*)&Ab[(rb + 8) * GST + kc];
            }
#pragma unroll
            for (int nt = 0; nt < 8; nt++) {
                const float2 b = *(const float2*)&Bb[(wn * 64 + nt * 8 + g) * GST + kc];
                mma8(acc[0][nt], a0[0].x, a1[0].x, a0[0].y, a1[0].y, b.x, b.y);
                mma8(acc[1][nt], a0[1].x, a1[1].x, a0[1].y, a1[1].y, b.x, b.y);
            }
        }
    }
#undef G_ISSUE

#pragma unroll
    for (int mt = 0; mt < 2; mt++) {
        const int r0 = m0 + wm * 32 + mt * 16 + g;
#pragma unroll
        for (int nt = 0; nt < 8; nt++) {
            const int c = n0 + wn * 64 + nt * 8 + tg * 2;
            const float bv0 = bias[c], bv1 = bias[c + 1];
            float v00 = acc[mt][nt][0] + bv0, v01 = acc[mt][nt][1] + bv1;
            float v10 = acc[mt][nt][2] + bv0, v11 = acc[mt][nt][3] + bv1;
            if (MODE >= 1) {
                v00 = to_tf32(v00 * scale); v01 = to_tf32(v01 * scale);
                v10 = to_tf32(v10 * scale); v11 = to_tf32(v11 * scale);
                const int h = c >> 6, dk = c & 63;
                const int bb = r0 >> 11, ss = r0 & 2047;
                if (MODE == 1) {
                    float* o0 = &out[(((bb * H_ + h) * S_) + ss) * DK_ + dk];
                    *(float2*)o0 = make_float2(v00, v01);
                    *(float2*)(o0 + 8 * DK_) = make_float2(v10, v11);
                } else {
                    float* o0 = &out[(((bb * H_ + h) * DK_) + dk) * S_ + ss];
                    o0[0] = v00;
                    o0[8] = v10;
                    o0[S_] = v01;
                    o0[S_ + 8] = v11;
                }
            } else {
                *(float2*)&out[r0 * D_ + c] = make_float2(v00, v01);
                *(float2*)&out[(r0 + 8) * D_ + c] = make_float2(v10, v11);
            }
        }
    }
}

// 0.125 * log2(e)
#define QSCALE 0.1803368801111204f

__global__ __launch_bounds__(256, 2) void qkv_kernel(
    const float* __restrict__ bq, const float* __restrict__ bk,
    const float* __restrict__ bv)
{
    extern __shared__ __align__(16) float sm[];
    float* As = sm;
    float* Bs = sm + 2 * GSTG2;
    if (blockIdx.z == 0)      gemm_tc<1>(As, Bs, g_rq, g_rwq, bq, g_q, QSCALE);
    else if (blockIdx.z == 1) gemm_tc<1>(As, Bs, g_rk, g_rwk, bk, g_k, 1.0f);
    else                      gemm_tc<2>(As, Bs, g_rv, g_rwv, bv, g_vT, 1.0f);
}

__global__ __launch_bounds__(256, 2) void oproj_kernel(
    const float* __restrict__ bo, float* __restrict__ out)
{
    extern __shared__ __align__(16) float sm[];
    float* As = sm;
    float* Bs = sm + 2 * GSTG2;
    gemm_tc<0>(As, Bs, g_x, g_rwo, bo, out, 1.0f);
}

// ---------------------------------------------------------------------------
// Flash attention (unchanged from R8/R9): Br=256, Q/P in registers,
// XOR-swizzled stride-64 K/V smem, double-buffered cp.async, base-2 softmax.
// ---------------------------------------------------------------------------
#define ATKV (64 * 64)
#define ATTN_SMEM_BYTES (4 * ATKV * 4)   // 65536 B

__global__ __launch_bounds__(256) void attn_kernel(const int* __restrict__ mask)
{
    extern __shared__ __align__(16) float sm[];
    float* Ks = sm;
    float* Vt = sm + 2 * ATKV;

    const int tid = threadIdx.x;
    const int lane = tid & 31, wid = tid >> 5;
    const int g = lane >> 2, tg = lane & 3;
    const int w32 = wid * 32;
    const int q0 = blockIdx.x * 256;
    const int bh = blockIdx.y;

    const float* Qg = g_q + bh * S_ * DK_;
    const float* Kg = g_k + bh * S_ * DK_;
    const float* Vg = g_vT + bh * DK_ * S_;

    const uint32_t KsU = smem_u32(Ks), VtU = smem_u32(Vt);
    const int r = tid >> 2, qd = tid & 3;
    const int rsw = (r & 7) * 8;

#define KV_ISSUE(s, t)                                                          \
    do {                                                                        \
        const float* ksrc = Kg + ((t) * 64 + r) * DK_ + qd * 16;                \
        const float* vsrc = Vg + r * S_ + (t) * 64 + qd * 16;                   \
        const uint32_t kdb = KsU + (uint32_t)((s) * ATKV + r * 64) * 4;         \
        const uint32_t vdb = VtU + (uint32_t)((s) * ATKV + r * 64) * 4;         \
        _Pragma("unroll")                                                       \
        for (int j = 0; j < 4; j++) {                                           \
            const uint32_t co = (uint32_t)((qd * 16 + j * 4) ^ rsw) * 4;        \
            cp_async16(kdb + co, ksrc + j * 4);                                 \
            cp_async16(vdb + co, vsrc + j * 4);                                 \
        }                                                                       \
    } while (0)

    KV_ISSUE(0, 0);
    CP_COMMIT();
    KV_ISSUE(1, 1);
    CP_COMMIT();

    float2 qA[2][8], qB[2][8];
#pragma unroll
    for (int mt = 0; mt < 2; mt++) {
        const float* qlo = Qg + (q0 + w32 + mt * 16 + g) * DK_ + tg * 2;
        const float* qhi = qlo + 8 * DK_;
#pragma unroll
        for (int kk = 0; kk < 8; kk++) {
            qA[mt][kk] = *(const float2*)(qlo + kk * 8);
            qB[mt][kk] = *(const float2*)(qhi + kk * 8);
        }
    }

    float mr[2][2], lr2[2][2];
#pragma unroll
    for (int mt = 0; mt < 2; mt++) {
        mr[mt][0] = -1e30f; mr[mt][1] = -1e30f;
        lr2[mt][0] = 0.0f;  lr2[mt][1] = 0.0f;
    }
    float o[2][8][4];
#pragma unroll
    for (int mt = 0; mt < 2; mt++)
#pragma unroll
        for (int nt = 0; nt < 8; nt++)
#pragma unroll
            for (int i = 0; i < 4; i++) o[mt][nt][i] = 0.0f;

    const int mrow = blockIdx.x * 2;

    for (int kt = 0; kt < 32; kt++) {
        CP_WAIT1();
        __syncthreads();
        const float* Ksb = Ks + (kt & 1) * ATKV;
        const float* Vtb = Vt + (kt & 1) * ATKV;

        float s[2][8][4];
#pragma unroll
        for (int mt = 0; mt < 2; mt++)
#pragma unroll
            for (int nt = 0; nt < 8; nt++)
#pragma unroll
                for (int i = 0; i < 4; i++) s[mt][nt][i] = 0.0f;

#pragma unroll
        for (int kk = 0; kk < 8; kk++) {
            const int fo = 8 * (kk ^ g) + tg * 2;
#pragma unroll
            for (int nt = 0; nt < 8; nt++) {
                const float2 bv = *(const float2*)&Ksb[(nt * 8 + g) * 64 + fo];
                mma8(s[0][nt], qA[0][kk].x, qB[0][kk].x, qA[0][kk].y, qB[0][kk].y,
                     bv.x, bv.y);
                mma8(s[1][nt], qA[1][kk].x, qB[1][kk].x, qA[1][kk].y, qB[1][kk].y,
                     bv.x, bv.y);
            }
        }

        if (!(g_mflag[mrow * 32 + kt] & g_mflag[(mrow + 1) * 32 + kt])) {
            const int k0 = kt * 64;
#pragma unroll
            for (int mt = 0; mt < 2; mt++) {
                const int* mp0 = mask + (q0 + w32 + mt * 16 + g) * S_ + k0 + tg * 2;
                const int* mp1 = mp0 + 8 * S_;
#pragma unroll
                for (int nt = 0; nt < 8; nt++) {
                    const int2 m0v = *(const int2*)(mp0 + nt * 8);
                    const int2 m1v = *(const int2*)(mp1 + nt * 8);
                    if (m0v.x == 0) s[mt][nt][0] = -1e9f;
                    if (m0v.y == 0) s[mt][nt][1] = -1e9f;
                    if (m1v.x == 0) s[mt][nt][2] = -1e9f;
                    if (m1v.y == 0) s[mt][nt][3] = -1e9f;
                }
            }
        }

#pragma unroll
        for (int mt = 0; mt < 2; mt++) {
            float mx0 = -1e30f, mx1 = -1e30f;
#pragma unroll
            for (int nt = 0; nt < 8; nt++) {
                mx0 = fmaxf(mx0, fmaxf(s[mt][nt][0], s[mt][nt][1]));
                mx1 = fmaxf(mx1, fmaxf(s[mt][nt][2], s[mt][nt][3]));
            }
            mx0 = fmaxf(mx0, __shfl_xor_sync(0xffffffffu, mx0, 1));
            mx0 = fmaxf(mx0, __shfl_xor_sync(0xffffffffu, mx0, 2));
            mx1 = fmaxf(mx1, __shfl_xor_sync(0xffffffffu, mx1, 1));
            mx1 = fmaxf(mx1, __shfl_xor_sync(0xffffffffu, mx1, 2));
            const float mn0 = fmaxf(mr[mt][0], mx0);
            const float mn1 = fmaxf(mr[mt][1], mx1);
            const float al0 = exp2f(mr[mt][0] - mn0);
            const float al1 = exp2f(mr[mt][1] - mn1);
            mr[mt][0] = mn0; mr[mt][1] = mn1;

            float sum0 = 0.0f, sum1 = 0.0f;
#pragma unroll
            for (int nt = 0; nt < 8; nt++) {
                const float p0 = exp2f(s[mt][nt][0] - mn0);
                const float p1 = exp2f(s[mt][nt][1] - mn0);
                const float p2 = exp2f(s[mt][nt][2] - mn1);
                const float p3 = exp2f(s[mt][nt][3] - mn1);
                sum0 += p0 + p1;
                sum1 += p2 + p3;
                s[mt][nt][0] = to_tf32(p0);
                s[mt][nt][1] = to_tf32(p1);
                s[mt][nt][2] = to_tf32(p2);
                s[mt][nt][3] = to_tf32(p3);
                o[mt][nt][0] *= al0; o[mt][nt][1] *= al0;
                o[mt][nt][2] *= al1; o[mt][nt][3] *= al1;
            }
            sum0 += __shfl_xor_sync(0xffffffffu, sum0, 1);
            sum0 += __shfl_xor_sync(0xffffffffu, sum0, 2);
            sum1 += __shfl_xor_sync(0xffffffffu, sum1, 1);
            sum1 += __shfl_xor_sync(0xffffffffu, sum1, 2);
            lr2[mt][0] = lr2[mt][0] * al0 + sum0;
            lr2[mt][1] = lr2[mt][1] * al1 + sum1;
        }

#pragma unroll
        for (int kk = 0; kk < 8; kk++) {
            const int fo = 8 * (kk ^ g) + tg * 2;
#pragma unroll
            for (int nt = 0; nt < 8; nt++) {
                const float2 bv = *(const float2*)&Vtb[(nt * 8 + g) * 64 + fo];
                mma8(o[0][nt], s[0][kk][0], s[0][kk][2], s[0][kk][1], s[0][kk][3],
                     bv.x, bv.y);
                mma8(o[1][nt], s[1][kk][0], s[1][kk][2], s[1][kk][1], s[1][kk][3],
                     bv.x, bv.y);
            }
        }

        __syncthreads();
        KV_ISSUE(kt & 1, (kt + 2) & 31);
        CP_COMMIT();
    }
#undef KV_ISSUE

    CP_WAIT0();

    const int bb = bh >> 4, h = bh & 15;
#pragma unroll
    for (int mt = 0; mt < 2; mt++) {
        const float inv0 = 1.0f / lr2[mt][0];
        const float inv1 = 1.0f / lr2[mt][1];
        const int r0 = q0 + w32 + mt * 16 + g;
        float* O0 = &g_x[(bb * S_ + r0) * D_ + h * DK_ + tg * 2];
        float* O1 = O0 + 8 * D_;
#pragma unroll
        for (int nt = 0; nt < 8; nt++) {
            *(float2*)(O0 + nt * 8) =
                make_float2(to_tf32(o[mt][nt][0] * inv0), to_tf32(o[mt][nt][1] * inv0));
            *(float2*)(O1 + nt * 8) =
                make_float2(to_tf32(o[mt][nt][2] * inv1), to_tf32(o[mt][nt][3] * inv1));
        }
    }
}

// ---------------------------------------------------------------------------
extern "C" void kernel_launch(void* const* d_in, const int* in_sizes, int n_in,
                              void* d_out, int out_size)
{
    (void)in_sizes; (void)n_in; (void)out_size;
    const float* q    = (const float*)d_in[0];
    const float* k    = (const float*)d_in[1];
    const float* v    = (const float*)d_in[2];
    const int*   mask = (const int*)d_in[3];
    const float* wq   = (const float*)d_in[4];
    const float* bq   = (const float*)d_in[5];
    const float* wk   = (const float*)d_in[6];
    const float* bk   = (const float*)d_in[7];
    const float* wv   = (const float*)d_in[8];
    const float* bv   = (const float*)d_in[9];
    const float* wo   = (const float*)d_in[10];
    const float* bo   = (const float*)d_in[11];
    float* out = (float*)d_out;

    static bool attrs_set = false;
    if (!attrs_set) {
        cudaFuncSetAttribute(qkv_kernel, cudaFuncAttributeMaxDynamicSharedMemorySize,
                             GEMM_SMEM_BYTES);
        cudaFuncSetAttribute(oproj_kernel, cudaFuncAttributeMaxDynamicSharedMemorySize,
                             GEMM_SMEM_BYTES);
        cudaFuncSetAttribute(attn_kernel, cudaFuncAttributeMaxDynamicSharedMemorySize,
                             ATTN_SMEM_BYTES);
        attrs_set = true;
    }

    // Prepass (3 launches so qkv is the 4th = ncu capture slot)
    dim3 ga(512, 3);
    pre_act_kernel<<<ga, 256>>>(q, k, v);
    dim3 gw(256, 4);
    pre_w_kernel<<<gw, 256>>>(wq, wk, wv, wo);
    pre_mask_kernel<<<512, 256>>>(mask);

    // QKV projections (V writes g_vT directly)
    dim3 gqkv(D_ / 128, M_ / 128, 3);
    qkv_kernel<<<gqkv, 256, GEMM_SMEM_BYTES>>>(bq, bk, bv);

    // Attention
    dim3 gattn(S_ / 256, B_ * H_);
    attn_kernel<<<gattn, 256, ATTN_SMEM_BYTES>>>(mask);

    // Output projection
    dim3 gop(D_ / 128, M_ / 128);
    oproj_kernel<<<gop, 256, GEMM_SMEM_BYTES>>>(bo, out);
}

// round 11
// speedup vs baseline: 1.2487x; 1.0232x over previous
#include <cuda_runtime.h>
#include <cstdint>

#define B_ 4
#define S_ 2048
#define D_ 1024
#define H_ 16
#define DK_ 64
#define M_ (B_ * S_)   // 8192

__device__ float g_q[M_ * D_];     // [B,H,S,DK] tf32, q pre-scaled by 0.125*log2e
__device__ float g_k[M_ * D_];     // [B,H,S,DK] tf32
__device__ float g_vT[M_ * D_];    // [B,H,DK,S] tf32 (V projected + transposed)
__device__ float g_x[M_ * D_];     // [B,S,D] attention out, tf32-rounded
__device__ float g_rq[M_ * D_];
__device__ float g_rk[M_ * D_];
__device__ float g_rv[M_ * D_];
__device__ float g_rwq[D_ * D_];
__device__ float g_rwk[D_ * D_];
__device__ float g_rwv[D_ * D_];
__device__ float g_rwo[D_ * D_];
__device__ int   g_mflag[16 * 32];

__device__ __forceinline__ float to_tf32(float x) {
    float r;
    asm("cvt.rna.tf32.f32 %0, %1;" : "=f"(r) : "f"(x));
    return r;
}

__device__ __forceinline__ void mma8(float c[4], float a0, float a1, float a2, float a3,
                                     float b0, float b1) {
    asm volatile(
        "mma.sync.aligned.m16n8k8.row.col.f32.tf32.tf32.f32 "
        "{%0,%1,%2,%3}, {%4,%5,%6,%7}, {%8,%9}, {%0,%1,%2,%3};"
        : "+f"(c[0]), "+f"(c[1]), "+f"(c[2]), "+f"(c[3])
        : "r"(__float_as_uint(a0)), "r"(__float_as_uint(a1)),
          "r"(__float_as_uint(a2)), "r"(__float_as_uint(a3)),
          "r"(__float_as_uint(b0)), "r"(__float_as_uint(b1)));
}

__device__ __forceinline__ uint32_t smem_u32(const void* p) {
    return (uint32_t)__cvta_generic_to_shared(p);
}
__device__ __forceinline__ void cp_async16(uint32_t dst, const float* src) {
    asm volatile("cp.async.ca.shared.global [%0], [%1], 16;" :: "r"(dst), "l"(src));
}
#define CP_COMMIT() asm volatile("cp.async.commit_group;")
#define CP_WAIT1()  asm volatile("cp.async.wait_group 1;")
#define CP_WAIT0()  asm volatile("cp.async.wait_group 0;")

// ---------------------------------------------------------------------------
// Prepass kernels
// ---------------------------------------------------------------------------
__global__ __launch_bounds__(256) void pre_act_kernel(
    const float* __restrict__ q, const float* __restrict__ k, const float* __restrict__ v)
{
    const int which = blockIdx.y;
    const float* src = (which == 0) ? q : (which == 1) ? k : v;
    float* dst = (which == 0) ? g_rq : (which == 1) ? g_rk : g_rv;
    const int n4 = M_ * D_ / 4;
    const int stride = gridDim.x * blockDim.x;
    for (int i = blockIdx.x * blockDim.x + threadIdx.x; i < n4; i += stride) {
        float4 t = ((const float4*)src)[i];
        ((float4*)dst)[i] =
            make_float4(to_tf32(t.x), to_tf32(t.y), to_tf32(t.z), to_tf32(t.w));
    }
}

__global__ __launch_bounds__(256) void pre_w_kernel(
    const float* __restrict__ wq, const float* __restrict__ wk,
    const float* __restrict__ wv, const float* __restrict__ wo)
{
    const int which = blockIdx.y;
    const float* src = (which == 0) ? wq : (which == 1) ? wk : (which == 2) ? wv : wo;
    float* dst = (which == 0) ? g_rwq : (which == 1) ? g_rwk : (which == 2) ? g_rwv : g_rwo;
    const int n4 = D_ * D_ / 4;
    const int stride = gridDim.x * blockDim.x;
    for (int i = blockIdx.x * blockDim.x + threadIdx.x; i < n4; i += stride) {
        float4 t = ((const float4*)src)[i];
        ((float4*)dst)[i] =
            make_float4(to_tf32(t.x), to_tf32(t.y), to_tf32(t.z), to_tf32(t.w));
    }
}

__global__ __launch_bounds__(256) void pre_mask_kernel(const int* __restrict__ mask)
{
    const int qt = blockIdx.x >> 5, kt = blockIdx.x & 31;
    const int tid = threadIdx.x;
    const int r = tid >> 1, h = tid & 1;
    const int* p = mask + (qt * 128 + r) * S_ + kt * 64 + h * 32;
    bool ok = true;
#pragma unroll
    for (int j = 0; j < 8; j++) {
        int4 mv = *(const int4*)(p + j * 4);
        ok &= (mv.x != 0) & (mv.y != 0) & (mv.z != 0) & (mv.w != 0);
    }
    const int all = __syncthreads_and((int)ok);
    if (tid == 0) g_mflag[qt * 32 + kt] = all;
}

// ---------------------------------------------------------------------------
// tf32 tensor-core GEMM: BM=128, BN=256, BK=32, 2-stage double buffer,
// 8 warps as 2m x 4n, warp tile 64x64 (LDS:mma = 0.5). Stride-40 smem,
// conflict-free float2 fragments, k-slot permutation on A and B.
// MODE 0: out [M,D]; 1: head-split [B,H,S,DK]; 2: split+transposed [B,H,DK,S].
// ---------------------------------------------------------------------------
#define GST 40
#define ASTG (128 * GST)
#define BSTG (256 * GST)
#define GEMM_SMEM_BYTES ((2 * ASTG + 2 * BSTG) * 4)   // 122880 B

template <int MODE>
__device__ __forceinline__ void gemm_tc(
    float* As, float* Bs,
    const float* __restrict__ X, const float* __restrict__ W,
    const float* __restrict__ bias, float* __restrict__ out, float scale)
{
    const int tid = threadIdx.x;
    const int lane = tid & 31, wid = tid >> 5;
    const int g = lane >> 2, tg = lane & 3;
    const int wm = wid >> 2, wn = wid & 3;      // 2m x 4n warps
    const int m0 = blockIdx.y * 128, n0 = blockIdx.x * 256;

    const uint32_t AsU = smem_u32(As), BsU = smem_u32(Bs);
    const int lr = tid >> 1;            // row 0..127
    const int lsg = (tid & 1) * 16;     // col 0 or 16

    const float* xrow = X + (long long)(m0 + lr) * D_ + lsg;
    const float* wrow0 = W + (long long)(n0 + lr) * D_ + lsg;
    const float* wrow1 = W + (long long)(n0 + lr + 128) * D_ + lsg;
    const uint32_t adst = AsU + (uint32_t)(lr * GST + lsg) * 4;
    const uint32_t bdst0 = BsU + (uint32_t)(lr * GST + lsg) * 4;
    const uint32_t bdst1 = bdst0 + (uint32_t)(128 * GST) * 4;

#define G_ISSUE(s, kb)                                        \
    do {                                                      \
        const float* xs = xrow + (kb) * 32;                   \
        const float* w0 = wrow0 + (kb) * 32;                  \
        const float* w1 = wrow1 + (kb) * 32;                  \
        const uint32_t ao = (uint32_t)((s) * ASTG) * 4;       \
        const uint32_t bo = (uint32_t)((s) * BSTG) * 4;       \
        cp_async16(adst + ao,      xs);                       \
        cp_async16(adst + ao + 16, xs + 4);                   \
        cp_async16(adst + ao + 32, xs + 8);                   \
        cp_async16(adst + ao + 48, xs + 12);                  \
        cp_async16(bdst0 + bo,      w0);                      \
        cp_async16(bdst0 + bo + 16, w0 + 4);                  \
        cp_async16(bdst0 + bo + 32, w0 + 8);                  \
        cp_async16(bdst0 + bo + 48, w0 + 12);                 \
        cp_async16(bdst1 + bo,      w1);                      \
        cp_async16(bdst1 + bo + 16, w1 + 4);                  \
        cp_async16(bdst1 + bo + 32, w1 + 8);                  \
        cp_async16(bdst1 + bo + 48, w1 + 12);                 \
    } while (0)

    float acc[4][8][4];
#pragma unroll
    for (int mt = 0; mt < 4; mt++)
#pragma unroll
        for (int nt = 0; nt < 8; nt++)
#pragma unroll
            for (int i = 0; i < 4; i++) acc[mt][nt][i] = 0.0f;

    G_ISSUE(0, 0);
    CP_COMMIT();

    for (int it = 0; it < 32; it++) {
        CP_WAIT0();
        __syncthreads();
        if (it < 31) {
            G_ISSUE((it + 1) & 1, it + 1);
            CP_COMMIT();
        }

        const float* Ab = As + (it & 1) * ASTG;
        const float* Bb = Bs + (it & 1) * BSTG;
#pragma unroll
        for (int kk = 0; kk < 4; kk++) {
            const int kc = kk * 8 + tg * 2;   // k cols 2tg,2tg+1 -> slots tg,tg+4
            float2 a0[4], a1[4];
#pragma unroll
            for (int mt = 0; mt < 4; mt++) {
                const int rb = wm * 64 + mt * 16 + g;
                a0[mt] = *(const float2*)&Ab[rb * GST + kc];
                a1[mt] = *(const float2*)&Ab[(rb + 8) * GST + kc];
            }
#pragma unroll
            for (int nt = 0; nt < 8; nt++) {
                const float2 b = *(const float2*)&Bb[(wn * 64 + nt * 8 + g) * GST + kc];
#pragma unroll
                for (int mt = 0; mt < 4; mt++)
                    mma8(acc[mt][nt], a0[mt].x, a1[mt].x, a0[mt].y, a1[mt].y, b.x, b.y);
            }
        }
    }
#undef G_ISSUE

#pragma unroll
    for (int mt = 0; mt < 4; mt++) {
        const int r0 = m0 + wm * 64 + mt * 16 + g;
#pragma unroll
        for (int nt = 0; nt < 8; nt++) {
            const int c = n0 + wn * 64 + nt * 8 + tg * 2;
            const float bv0 = bias[c], bv1 = bias[c + 1];
            float v00 = acc[mt][nt][0] + bv0, v01 = acc[mt][nt][1] + bv1;
            float v10 = acc[mt][nt][2] + bv0, v11 = acc[mt][nt][3] + bv1;
            if (MODE >= 1) {
                v00 = to_tf32(v00 * scale); v01 = to_tf32(v01 * scale);
                v10 = to_tf32(v10 * scale); v11 = to_tf32(v11 * scale);
                const int h = c >> 6, dk = c & 63;
                const int bb = r0 >> 11, ss = r0 & 2047;
                if (MODE == 1) {
                    float* o0 = &out[(((bb * H_ + h) * S_) + ss) * DK_ + dk];
                    *(float2*)o0 = make_float2(v00, v01);
                    *(float2*)(o0 + 8 * DK_) = make_float2(v10, v11);
                } else {
                    float* o0 = &out[(((bb * H_ + h) * DK_) + dk) * S_ + ss];
                    o0[0] = v00;
                    o0[8] = v10;
                    o0[S_] = v01;
                    o0[S_ + 8] = v11;
                }
            } else {
                *(float2*)&out[r0 * D_ + c] = make_float2(v00, v01);
                *(float2*)&out[(r0 + 8) * D_ + c] = make_float2(v10, v11);
            }
        }
    }
}

// 0.125 * log2(e)
#define QSCALE 0.1803368801111204f

__global__ __launch_bounds__(256) void qkv_kernel(
    const float* __restrict__ bq, const float* __restrict__ bk,
    const float* __restrict__ bv)
{
    extern __shared__ __align__(16) float sm[];
    float* As = sm;
    float* Bs = sm + 2 * ASTG;
    if (blockIdx.z == 0)      gemm_tc<1>(As, Bs, g_rq, g_rwq, bq, g_q, QSCALE);
    else if (blockIdx.z == 1) gemm_tc<1>(As, Bs, g_rk, g_rwk, bk, g_k, 1.0f);
    else                      gemm_tc<2>(As, Bs, g_rv, g_rwv, bv, g_vT, 1.0f);
}

__global__ __launch_bounds__(256) void oproj_kernel(
    const float* __restrict__ bo, float* __restrict__ out)
{
    extern __shared__ __align__(16) float sm[];
    float* As = sm;
    float* Bs = sm + 2 * ASTG;
    gemm_tc<0>(As, Bs, g_x, g_rwo, bo, out, 1.0f);
}

// ---------------------------------------------------------------------------
// Flash attention (unchanged): Br=256, Q/P in registers, XOR-swizzled
// stride-64 K/V smem, double-buffered cp.async, base-2 softmax.
// ---------------------------------------------------------------------------
#define ATKV (64 * 64)
#define ATTN_SMEM_BYTES (4 * ATKV * 4)   // 65536 B

__global__ __launch_bounds__(256) void attn_kernel(const int* __restrict__ mask)
{
    extern __shared__ __align__(16) float sm[];
    float* Ks = sm;
    float* Vt = sm + 2 * ATKV;

    const int tid = threadIdx.x;
    const int lane = tid & 31, wid = tid >> 5;
    const int g = lane >> 2, tg = lane & 3;
    const int w32 = wid * 32;
    const int q0 = blockIdx.x * 256;
    const int bh = blockIdx.y;

    const float* Qg = g_q + bh * S_ * DK_;
    const float* Kg = g_k + bh * S_ * DK_;
    const float* Vg = g_vT + bh * DK_ * S_;

    const uint32_t KsU = smem_u32(Ks), VtU = smem_u32(Vt);
    const int r = tid >> 2, qd = tid & 3;
    const int rsw = (r & 7) * 8;

#define KV_ISSUE(s, t)                                                          \
    do {                                                                        \
        const float* ksrc = Kg + ((t) * 64 + r) * DK_ + qd * 16;                \
        const float* vsrc = Vg + r * S_ + (t) * 64 + qd * 16;                   \
        const uint32_t kdb = KsU + (uint32_t)((s) * ATKV + r * 64) * 4;         \
        const uint32_t vdb = VtU + (uint32_t)((s) * ATKV + r * 64) * 4;         \
        _Pragma("unroll")                                                       \
        for (int j = 0; j < 4; j++) {                                           \
            const uint32_t co = (uint32_t)((qd * 16 + j * 4) ^ rsw) * 4;        \
            cp_async16(kdb + co, ksrc + j * 4);                                 \
            cp_async16(vdb + co, vsrc + j * 4);                                 \
        }                                                                       \
    } while (0)

    KV_ISSUE(0, 0);
    CP_COMMIT();
    KV_ISSUE(1, 1);
    CP_COMMIT();

    float2 qA[2][8], qB[2][8];
#pragma unroll
    for (int mt = 0; mt < 2; mt++) {
        const float* qlo = Qg + (q0 + w32 + mt * 16 + g) * DK_ + tg * 2;
        const float* qhi = qlo + 8 * DK_;
#pragma unroll
        for (int kk = 0; kk < 8; kk++) {
            qA[mt][kk] = *(const float2*)(qlo + kk * 8);
            qB[mt][kk] = *(const float2*)(qhi + kk * 8);
        }
    }

    float mr[2][2], lr2[2][2];
#pragma unroll
    for (int mt = 0; mt < 2; mt++) {
        mr[mt][0] = -1e30f; mr[mt][1] = -1e30f;
        lr2[mt][0] = 0.0f;  lr2[mt][1] = 0.0f;
    }
    float o[2][8][4];
#pragma unroll
    for (int mt = 0; mt < 2; mt++)
#pragma unroll
        for (int nt = 0; nt < 8; nt++)
#pragma unroll
            for (int i = 0; i < 4; i++) o[mt][nt][i] = 0.0f;

    const int mrow = blockIdx.x * 2;

    for (int kt = 0; kt < 32; kt++) {
        CP_WAIT1();
        __syncthreads();
        const float* Ksb = Ks + (kt & 1) * ATKV;
        const float* Vtb = Vt + (kt & 1) * ATKV;

        float s[2][8][4];
#pragma unroll
        for (int mt = 0; mt < 2; mt++)
#pragma unroll
            for (int nt = 0; nt < 8; nt++)
#pragma unroll
                for (int i = 0; i < 4; i++) s[mt][nt][i] = 0.0f;

#pragma unroll
        for (int kk = 0; kk < 8; kk++) {
            const int fo = 8 * (kk ^ g) + tg * 2;
#pragma unroll
            for (int nt = 0; nt < 8; nt++) {
                const float2 bv = *(const float2*)&Ksb[(nt * 8 + g) * 64 + fo];
                mma8(s[0][nt], qA[0][kk].x, qB[0][kk].x, qA[0][kk].y, qB[0][kk].y,
                     bv.x, bv.y);
                mma8(s[1][nt], qA[1][kk].x, qB[1][kk].x, qA[1][kk].y, qB[1][kk].y,
                     bv.x, bv.y);
            }
        }

        if (!(g_mflag[mrow * 32 + kt] & g_mflag[(mrow + 1) * 32 + kt])) {
            const int k0 = kt * 64;
#pragma unroll
            for (int mt = 0; mt < 2; mt++) {
                const int* mp0 = mask + (q0 + w32 + mt * 16 + g) * S_ + k0 + tg * 2;
                const int* mp1 = mp0 + 8 * S_;
#pragma unroll
                for (int nt = 0; nt < 8; nt++) {
                    const int2 m0v = *(const int2*)(mp0 + nt * 8);
                    const int2 m1v = *(const int2*)(mp1 + nt * 8);
                    if (m0v.x == 0) s[mt][nt][0] = -1e9f;
                    if (m0v.y == 0) s[mt][nt][1] = -1e9f;
                    if (m1v.x == 0) s[mt][nt][2] = -1e9f;
                    if (m1v.y == 0) s[mt][nt][3] = -1e9f;
                }
            }
        }

#pragma unroll
        for (int mt = 0; mt < 2; mt++) {
            float mx0 = -1e30f, mx1 = -1e30f;
#pragma unroll
            for (int nt = 0; nt < 8; nt++) {
                mx0 = fmaxf(mx0, fmaxf(s[mt][nt][0], s[mt][nt][1]));
                mx1 = fmaxf(mx1, fmaxf(s[mt][nt][2], s[mt][nt][3]));
            }
            mx0 = fmaxf(mx0, __shfl_xor_sync(0xffffffffu, mx0, 1));
            mx0 = fmaxf(mx0, __shfl_xor_sync(0xffffffffu, mx0, 2));
            mx1 = fmaxf(mx1, __shfl_xor_sync(0xffffffffu, mx1, 1));
            mx1 = fmaxf(mx1, __shfl_xor_sync(0xffffffffu, mx1, 2));
            const float mn0 = fmaxf(mr[mt][0], mx0);
            const float mn1 = fmaxf(mr[mt][1], mx1);
            const float al0 = exp2f(mr[mt][0] - mn0);
            const float al1 = exp2f(mr[mt][1] - mn1);
            mr[mt][0] = mn0; mr[mt][1] = mn1;

            float sum0 = 0.0f, sum1 = 0.0f;
#pragma unroll
            for (int nt = 0; nt < 8; nt++) {
                const float p0 = exp2f(s[mt][nt][0] - mn0);
                const float p1 = exp2f(s[mt][nt][1] - mn0);
                const float p2 = exp2f(s[mt][nt][2] - mn1);
                const float p3 = exp2f(s[mt][nt][3] - mn1);
                sum0 += p0 + p1;
                sum1 += p2 + p3;
                s[mt][nt][0] = to_tf32(p0);
                s[mt][nt][1] = to_tf32(p1);
                s[mt][nt][2] = to_tf32(p2);
                s[mt][nt][3] = to_tf32(p3);
                o[mt][nt][0] *= al0; o[mt][nt][1] *= al0;
                o[mt][nt][2] *= al1; o[mt][nt][3] *= al1;
            }
            sum0 += __shfl_xor_sync(0xffffffffu, sum0, 1);
            sum0 += __shfl_xor_sync(0xffffffffu, sum0, 2);
            sum1 += __shfl_xor_sync(0xffffffffu, sum1, 1);
            sum1 += __shfl_xor_sync(0xffffffffu, sum1, 2);
            lr2[mt][0] = lr2[mt][0] * al0 + sum0;
            lr2[mt][1] = lr2[mt][1] * al1 + sum1;
        }

#pragma unroll
        for (int kk = 0; kk < 8; kk++) {
            const int fo = 8 * (kk ^ g) + tg * 2;
#pragma unroll
            for (int nt = 0; nt < 8; nt++) {
                const float2 bv = *(const float2*)&Vtb[(nt * 8 + g) * 64 + fo];
                mma8(o[0][nt], s[0][kk][0], s[0][kk][2], s[0][kk][1], s[0][kk][3],
                     bv.x, bv.y);
                mma8(o[1][nt], s[1][kk][0], s[1][kk][2], s[1][kk][1], s[1][kk][3],
                     bv.x, bv.y);
            }
        }

        __syncthreads();
        KV_ISSUE(kt & 1, (kt + 2) & 31);
        CP_COMMIT();
    }
#undef KV_ISSUE

    CP_WAIT0();

    const int bb = bh >> 4, h = bh & 15;
#pragma unroll
    for (int mt = 0; mt < 2; mt++) {
        const float inv0 = 1.0f / lr2[mt][0];
        const float inv1 = 1.0f / lr2[mt][1];
        const int r0 = q0 + w32 + mt * 16 + g;
        float* O0 = &g_x[(bb * S_ + r0) * D_ + h * DK_ + tg * 2];
        float* O1 = O0 + 8 * D_;
#pragma unroll
        for (int nt = 0; nt < 8; nt++) {
            *(float2*)(O0 + nt * 8) =
                make_float2(to_tf32(o[mt][nt][0] * inv0), to_tf32(o[mt][nt][1] * inv0));
            *(float2*)(O1 + nt * 8) =
                make_float2(to_tf32(o[mt][nt][2] * inv1), to_tf32(o[mt][nt][3] * inv1));
        }
    }
}

// ---------------------------------------------------------------------------
extern "C" void kernel_launch(void* const* d_in, const int* in_sizes, int n_in,
                              void* d_out, int out_size)
{
    (void)in_sizes; (void)n_in; (void)out_size;
    const float* q    = (const float*)d_in[0];
    const float* k    = (const float*)d_in[1];
    const float* v    = (const float*)d_in[2];
    const int*   mask = (const int*)d_in[3];
    const float* wq   = (const float*)d_in[4];
    const float* bq   = (const float*)d_in[5];
    const float* wk   = (const float*)d_in[6];
    const float* bk   = (const float*)d_in[7];
    const float* wv   = (const float*)d_in[8];
    const float* bv   = (const float*)d_in[9];
    const float* wo   = (const float*)d_in[10];
    const float* bo   = (const float*)d_in[11];
    float* out = (float*)d_out;

    static bool attrs_set = false;
    if (!attrs_set) {
        cudaFuncSetAttribute(qkv_kernel, cudaFuncAttributeMaxDynamicSharedMemorySize,
                             GEMM_SMEM_BYTES);
        cudaFuncSetAttribute(oproj_kernel, cudaFuncAttributeMaxDynamicSharedMemorySize,
                             GEMM_SMEM_BYTES);
        cudaFuncSetAttribute(attn_kernel, cudaFuncAttributeMaxDynamicSharedMemorySize,
                             ATTN_SMEM_BYTES);
        attrs_set = true;
    }

    // Prepass (3 launches so qkv is the 4th = ncu capture slot)
    dim3 ga(512, 3);
    pre_act_kernel<<<ga, 256>>>(q, k, v);
    dim3 gw(256, 4);
    pre_w_kernel<<<gw, 256>>>(wq, wk, wv, wo);
    pre_mask_kernel<<<512, 256>>>(mask);

    // QKV projections (BN=256; V writes g_vT directly)
    dim3 gqkv(D_ / 256, M_ / 128, 3);
    qkv_kernel<<<gqkv, 256, GEMM_SMEM_BYTES>>>(bq, bk, bv);

    // Attention
    dim3 gattn(S_ / 256, B_ * H_);
    attn_kernel<<<gattn, 256, ATTN_SMEM_BYTES>>>(mask);

    // Output projection
    dim3 gop(D_ / 256, M_ / 128);
    oproj_kernel<<<gop, 256, GEMM_SMEM_BYTES>>>(bo, out);
}